// round 14
// baseline (speedup 1.0000x reference)
#include <cuda_runtime.h>
#include <math.h>
#include <stdint.h>

// ---------------- problem constants ----------------
#define BB   16      // batch
#define LK   64      // source length
#define LQ   64      // query length
#define DD   300     // embedding dim
#define HH   512     // encoder hidden
#define H2   1024    // 2*H (decoder hidden / enc_out channels)
#define HG   2048    // 4*H  encoder gates
#define DG   4096    // 8*H  decoder gates
#define VV   10000   // vocab

#define NBLK 128
#define NTHR 256

// ---------------- scratch (device globals; no allocation) ----------------
__device__ float g_xs_src[BB * LK * DD];
__device__ float g_xs_prev[BB * LQ * DD];
__device__ float g_xg_f[BB * LK * HG];
__device__ float g_xg_b[BB * LK * HG];
__device__ float g_xg_d[BB * LQ * DG];
__device__ float g_ce[2 * BB * HH];
__device__ float g_heT[2 * HH * BB];  // enc h: (dir, j, b)
__device__ float g_cd[BB * H2];
__device__ float g_hdT[H2 * BB];      // dec h: (jj, b)
__device__ float g_enc[BB * LK * H2];
__device__ float g_Kb[BB * LK * H2];
__device__ float g_Vb[BB * LK * H2];
__device__ float g_att[BB * LQ * LK];
__device__ float g_cat[BB * LQ * 2 * H2];
__device__ float g_x1[BB * LQ * H2];

// grid barrier state (generation counter; self-resetting, replay-safe)
__device__ unsigned g_bar_cnt = 0;
__device__ unsigned g_bar_gen = 0;

__device__ __forceinline__ float sigf(float x) { return 1.f / (1.f + expf(-x)); }

__device__ __forceinline__ void gbar() {
    __syncthreads();
    if (threadIdx.x == 0) {
        volatile unsigned* genp = &g_bar_gen;
        __threadfence();
        unsigned g = *genp;
        if (atomicAdd(&g_bar_cnt, 1u) == NBLK - 1) {
            g_bar_cnt = 0;
            __threadfence();
            *genp = g + 1;
        } else {
            while (*genp == g) { }
            __threadfence();
        }
    }
    __syncthreads();
}

// ---------------- tf32 helpers (legacy mma.sync path) ----------
__device__ __forceinline__ unsigned f2tf32(float f) {
    unsigned r;
    asm("cvt.rna.tf32.f32 %0, %1;" : "=r"(r) : "f"(f));
    return r;
}

__device__ __forceinline__ void mma1688(float c[4], const unsigned a[4], const unsigned b[2]) {
    asm volatile(
        "mma.sync.aligned.m16n8k8.row.col.f32.tf32.tf32.f32 "
        "{%0,%1,%2,%3}, {%4,%5,%6,%7}, {%8,%9}, {%0,%1,%2,%3};"
        : "+f"(c[0]), "+f"(c[1]), "+f"(c[2]), "+f"(c[3])
        : "r"(a[0]), "r"(a[1]), "r"(a[2]), "r"(a[3]), "r"(b[0]), "r"(b[1]));
}

// ---------------- small utility kernels ----------------
__global__ void k_zero_states() {
    int i = blockIdx.x * blockDim.x + threadIdx.x;
    int n = 2 * BB * HH;
    if (i < n) { g_ce[i] = 0.f; g_heT[i] = 0.f; }
}

__global__ void k_embed(const int* __restrict__ idx, const float* __restrict__ emb,
                        float* __restrict__ out, int rows) {
    int i = blockIdx.x * blockDim.x + threadIdx.x;
    if (i < rows * DD) {
        int r = i / DD, d = i - r * DD;
        out[i] = emb[(long)idx[r] * DD + d];
    }
}

// ---------------- tf32 tensor-core GEMM, 128x64 tile, 2 CTAs/SM -----------------
// C[M,N] = A[M,K] @ W[N,K]^T (+bias)(+tanh). 256 threads = 8 warps (4m x 2n),
// warp tile 32x32, mma.sync m16n8k8 tf32, fp32 accumulate. M % 128 == 0 assumed
// safe (M=1024 at all call sites); N ragged OK.
#define ASTRIDE 36
__global__ void __launch_bounds__(256, 2)
k_tgemm(const float* __restrict__ A, const float* __restrict__ W,
        const float* __restrict__ bias, float* __restrict__ C,
        int M, int N, int K, int act) {
    __shared__ unsigned As[128 * ASTRIDE];   // [m][k], padded
    __shared__ unsigned Ws[64 * ASTRIDE];    // [n][k], padded
    const int tid = threadIdx.x;
    const int warp = tid >> 5, lane = tid & 31;
    const int wm = warp >> 1, wn = warp & 1;   // 4m x 2n warp grid
    const int gid = lane >> 2, tig = lane & 3;
    const int m0 = blockIdx.y * 128, n0 = blockIdx.x * 64;
    float acc[2][4][4] = {};   // [mi][ni][creg]
    const int nch = (K + 31) / 32;

    for (int ch = 0; ch < nch; ch++) {
        const int kk = ch * 32;
        __syncthreads();
        // ---- stage A: 128 rows x 32 k ----
        #pragma unroll
        for (int s = 0; s < 4; s++) {
            int idx = tid + s * 256;
            int row = idx >> 3, c4 = (idx & 7) * 4;
            int kb = kk + c4;
            float4 va = make_float4(0.f, 0.f, 0.f, 0.f);
            if (m0 + row < M) {
                if (kb + 3 < K) va = *(const float4*)(A + (long)(m0 + row) * K + kb);
                else {
                    const float* p = A + (long)(m0 + row) * K;
                    va.x = (kb + 0 < K) ? p[kb + 0] : 0.f;
                    va.y = (kb + 1 < K) ? p[kb + 1] : 0.f;
                    va.z = (kb + 2 < K) ? p[kb + 2] : 0.f;
                    va.w = (kb + 3 < K) ? p[kb + 3] : 0.f;
                }
            }
            uint4 ua;
            ua.x = f2tf32(va.x); ua.y = f2tf32(va.y);
            ua.z = f2tf32(va.z); ua.w = f2tf32(va.w);
            *(uint4*)(As + row * ASTRIDE + c4) = ua;
        }
        // ---- stage W: 64 rows x 32 k ----
        #pragma unroll
        for (int s = 0; s < 2; s++) {
            int idx = tid + s * 256;
            int row = idx >> 3, c4 = (idx & 7) * 4;
            int kb = kk + c4;
            float4 vw = make_float4(0.f, 0.f, 0.f, 0.f);
            if (n0 + row < N) {
                if (kb + 3 < K) vw = *(const float4*)(W + (long)(n0 + row) * K + kb);
                else {
                    const float* p = W + (long)(n0 + row) * K;
                    vw.x = (kb + 0 < K) ? p[kb + 0] : 0.f;
                    vw.y = (kb + 1 < K) ? p[kb + 1] : 0.f;
                    vw.z = (kb + 2 < K) ? p[kb + 2] : 0.f;
                    vw.w = (kb + 3 < K) ? p[kb + 3] : 0.f;
                }
            }
            uint4 uw;
            uw.x = f2tf32(vw.x); uw.y = f2tf32(vw.y);
            uw.z = f2tf32(vw.z); uw.w = f2tf32(vw.w);
            *(uint4*)(Ws + row * ASTRIDE + c4) = uw;
        }
        __syncthreads();

        // ---- compute: 4 x K=8 mma steps ----
        #pragma unroll
        for (int ki = 0; ki < 4; ki++) {
            const int k0 = ki * 8;
            unsigned a[2][4], b[4][2];
            #pragma unroll
            for (int mi = 0; mi < 2; mi++) {
                int mr = wm * 32 + mi * 16;
                a[mi][0] = As[(mr + gid)     * ASTRIDE + k0 + tig];
                a[mi][1] = As[(mr + gid + 8) * ASTRIDE + k0 + tig];
                a[mi][2] = As[(mr + gid)     * ASTRIDE + k0 + tig + 4];
                a[mi][3] = As[(mr + gid + 8) * ASTRIDE + k0 + tig + 4];
            }
            #pragma unroll
            for (int ni = 0; ni < 4; ni++) {
                int nr = wn * 32 + ni * 8;
                b[ni][0] = Ws[(nr + gid) * ASTRIDE + k0 + tig];
                b[ni][1] = Ws[(nr + gid) * ASTRIDE + k0 + tig + 4];
            }
            #pragma unroll
            for (int mi = 0; mi < 2; mi++)
                #pragma unroll
                for (int ni = 0; ni < 4; ni++)
                    mma1688(acc[mi][ni], a[mi], b[ni]);
        }
    }

    // epilogue
    #pragma unroll
    for (int mi = 0; mi < 2; mi++) {
        int m1 = m0 + wm * 32 + mi * 16 + gid;
        int m2 = m1 + 8;
        #pragma unroll
        for (int ni = 0; ni < 4; ni++) {
            int nc = n0 + wn * 32 + ni * 8 + 2 * tig;
            float b0 = 0.f, b1 = 0.f;
            if (bias) {
                if (nc < N)     b0 = bias[nc];
                if (nc + 1 < N) b1 = bias[nc + 1];
            }
            float v0 = acc[mi][ni][0] + b0;
            float v1 = acc[mi][ni][1] + b1;
            float v2 = acc[mi][ni][2] + b0;
            float v3 = acc[mi][ni][3] + b1;
            if (act == 1) { v0 = tanhf(v0); v1 = tanhf(v1); v2 = tanhf(v2); v3 = tanhf(v3); }
            if (m1 < M) {
                if (nc < N)     C[(long)m1 * N + nc]     = v0;
                if (nc + 1 < N) C[(long)m1 * N + nc + 1] = v1;
            }
            if (m2 < M) {
                if (nc < N)     C[(long)m2 * N + nc]     = v2;
                if (nc + 1 < N) C[(long)m2 * N + nc + 1] = v3;
            }
        }
    }
}

// ---------------- small batched GEMM for attention scores (fp32) ----------------
__global__ void k_gemm(const float* __restrict__ A, const float* __restrict__ W,
                       const float* __restrict__ bias, float* __restrict__ C,
                       int M, int N, int K, long sA, long sW, long sC, int act) {
    A += (long)blockIdx.z * sA;
    W += (long)blockIdx.z * sW;
    C += (long)blockIdx.z * sC;
    __shared__ float As[16][68];
    __shared__ float Ws[16][68];
    int m0 = blockIdx.y * 64, n0 = blockIdx.x * 64;
    int tx = threadIdx.x, ty = threadIdx.y;
    int tid = ty * 16 + tx;
    float acc[4][4] = {};
    for (int kk = 0; kk < K; kk += 16) {
        #pragma unroll
        for (int s = 0; s < 4; s++) {
            int e = tid + s * 256;
            int mm = e >> 4, k = e & 15;
            float va = 0.f, vw = 0.f;
            if (m0 + mm < M && kk + k < K) va = A[(long)(m0 + mm) * K + kk + k];
            if (n0 + mm < N && kk + k < K) vw = W[(long)(n0 + mm) * K + kk + k];
            As[k][mm] = va;
            Ws[k][mm] = vw;
        }
        __syncthreads();
        #pragma unroll
        for (int k = 0; k < 16; k++) {
            float a[4], w[4];
            #pragma unroll
            for (int i = 0; i < 4; i++) a[i] = As[k][ty * 4 + i];
            #pragma unroll
            for (int j = 0; j < 4; j++) w[j] = Ws[k][tx * 4 + j];
            #pragma unroll
            for (int i = 0; i < 4; i++)
                #pragma unroll
                for (int j = 0; j < 4; j++) acc[i][j] += a[i] * w[j];
        }
        __syncthreads();
    }
    #pragma unroll
    for (int i = 0; i < 4; i++) {
        int m = m0 + ty * 4 + i;
        if (m >= M) continue;
        #pragma unroll
        for (int j = 0; j < 4; j++) {
            int n = n0 + tx * 4 + j;
            if (n >= N) continue;
            float v = acc[i][j];
            if (bias) v += bias[n];
            if (act == 1) v = tanhf(v);
            C[(long)m * N + n] = v;
        }
    }
}

// ---------------- persistent recurrence kernel (1 grid barrier per step) ----------
// Each block owns 8 hidden units j and computes ALL FOUR gate rows for them,
// k-split 8-way within the block (one k-range per warp), smem-reduced, cell
// applied in-block. Weights read in native [n][k] layout (no transpose).
__global__ void __launch_bounds__(NTHR, 1)
k_recurrence(const float* __restrict__ efW, const float* __restrict__ ebW,
             const float* __restrict__ dW) {
    __shared__ float sh[8192];          // 32KB: h stage, then partial-reduce
    float4* shv = (float4*)sh;
    const int tid = threadIdx.x;
    const int p = tid & 31;             // (jloc, gate) pair: jloc = p>>2, g = p&3
    const int gg = p & 3, jloc = p >> 2;
    const int ksub = tid >> 5;          // 0..7 — warp-uniform k-range

    // ===================== encoder =====================
    {
        const int dir = blockIdx.x >> 6;        // 0..1
        const int j0 = (blockIdx.x & 63) * 8;   // 64 blocks per dir x 8 j
        const int j = j0 + jloc;
        const float* W = (dir ? ebW : efW) + (long)(gg * HH + j) * HH;
        const float* hT = g_heT + dir * HH * BB;
        const float* xg = dir ? g_xg_b : g_xg_f;
        const float* Wp = W + ksub * 64;

        for (int t = 0; t < LK; t++) {
            // stage h: 512 j x 16 b = 8192 floats
            #pragma unroll
            for (int i = 0; i < 8; i++)
                shv[tid + i * NTHR] = ((const float4*)hT)[tid + i * NTHR];
            __syncthreads();

            float acc[16] = {};
            float4 w0 = *(const float4*)(Wp);
            float4 w1 = *(const float4*)(Wp + 4);
            const float4* sh4 = (const float4*)sh;
            #pragma unroll
            for (int kq = 0; kq < 16; kq++) {
                float4 wc = (kq & 1) ? w1 : w0;
                if (kq + 2 < 16) {
                    float4 wn = *(const float4*)(Wp + (kq + 2) * 4);
                    if (kq & 1) w1 = wn; else w0 = wn;
                }
                int kb = ksub * 64 + kq * 4;
                #pragma unroll
                for (int i = 0; i < 4; i++) {
                    float w = (&wc.x)[i];
                    float4 h0 = sh4[(kb + i) * 4 + 0];
                    float4 h1 = sh4[(kb + i) * 4 + 1];
                    float4 h2 = sh4[(kb + i) * 4 + 2];
                    float4 h3 = sh4[(kb + i) * 4 + 3];
                    acc[0]  += h0.x * w; acc[1]  += h0.y * w; acc[2]  += h0.z * w; acc[3]  += h0.w * w;
                    acc[4]  += h1.x * w; acc[5]  += h1.y * w; acc[6]  += h1.z * w; acc[7]  += h1.w * w;
                    acc[8]  += h2.x * w; acc[9]  += h2.y * w; acc[10] += h2.z * w; acc[11] += h2.w * w;
                    acc[12] += h3.x * w; acc[13] += h3.y * w; acc[14] += h3.z * w; acc[15] += h3.w * w;
                }
            }
            __syncthreads();   // done reading h stage
            // partials: red[ksub][p][b]
            {
                float4* dst = (float4*)(sh + (ksub * 32 + p) * 16);
                dst[0] = make_float4(acc[0], acc[1], acc[2], acc[3]);
                dst[1] = make_float4(acc[4], acc[5], acc[6], acc[7]);
                dst[2] = make_float4(acc[8], acc[9], acc[10], acc[11]);
                dst[3] = make_float4(acc[12], acc[13], acc[14], acc[15]);
            }
            __syncthreads();
            // cell: 8 j x 16 b = 128 cells
            if (tid < 128) {
                int jl = tid >> 4, b = tid & 15;
                int jj = j0 + jl;
                int tt = dir ? (LK - 1 - t) : t;
                float gate[4];
                #pragma unroll
                for (int g = 0; g < 4; g++) {
                    int p2 = (jl << 2) | g;
                    float s = xg[((long)b * LK + tt) * HG + g * HH + jj];
                    #pragma unroll
                    for (int q = 0; q < 8; q++)
                        s += sh[(q * 32 + p2) * 16 + b];
                    gate[g] = s;
                }
                int si = dir * BB * HH + b * HH + jj;
                float c = sigf(gate[1]) * g_ce[si] + sigf(gate[0]) * tanhf(gate[2]);
                float h = sigf(gate[3]) * tanhf(c);
                g_ce[si] = c;
                g_heT[(long)dir * HH * BB + (long)jj * BB + b] = h;
                g_enc[((long)b * LK + tt) * H2 + dir * HH + jj] = h;
            }
            gbar();
        }
    }

    // ===================== decoder init =====================
    {
        int gt = blockIdx.x * NTHR + tid;
        if (gt < BB * H2) {
            int b = gt >> 10, jj = gt & (H2 - 1);
            int dir = jj & 1, j = jj >> 1;
            g_hdT[(long)jj * BB + b] = g_heT[(long)dir * HH * BB + (long)j * BB + b];
            g_cd[gt] = g_ce[dir * BB * HH + b * HH + j];
        }
    }
    gbar();

    // ===================== decoder =====================
    {
        const int j0 = blockIdx.x * 8;          // 128 blocks x 8 j = 1024
        const int j = j0 + jloc;
        const float* W = dW + (long)(gg * H2 + j) * H2;

        for (int t = 0; t < LQ; t++) {
            float acc[16] = {};
            #pragma unroll
            for (int half = 0; half < 2; half++) {
                // stage h half: 512 j x 16 b
                const float4* hsrc = (const float4*)(g_hdT + half * 512 * BB);
                #pragma unroll
                for (int i = 0; i < 8; i++)
                    shv[tid + i * NTHR] = hsrc[tid + i * NTHR];
                __syncthreads();

                const float* Wp = W + half * 512 + ksub * 64;
                float4 w0 = *(const float4*)(Wp);
                float4 w1 = *(const float4*)(Wp + 4);
                const float4* sh4 = (const float4*)sh;
                #pragma unroll
                for (int kq = 0; kq < 16; kq++) {
                    float4 wc = (kq & 1) ? w1 : w0;
                    if (kq + 2 < 16) {
                        float4 wn = *(const float4*)(Wp + (kq + 2) * 4);
                        if (kq & 1) w1 = wn; else w0 = wn;
                    }
                    int kb = ksub * 64 + kq * 4;
                    #pragma unroll
                    for (int i = 0; i < 4; i++) {
                        float w = (&wc.x)[i];
                        float4 h0 = sh4[(kb + i) * 4 + 0];
                        float4 h1 = sh4[(kb + i) * 4 + 1];
                        float4 h2 = sh4[(kb + i) * 4 + 2];
                        float4 h3 = sh4[(kb + i) * 4 + 3];
                        acc[0]  += h0.x * w; acc[1]  += h0.y * w; acc[2]  += h0.z * w; acc[3]  += h0.w * w;
                        acc[4]  += h1.x * w; acc[5]  += h1.y * w; acc[6]  += h1.z * w; acc[7]  += h1.w * w;
                        acc[8]  += h2.x * w; acc[9]  += h2.y * w; acc[10] += h2.z * w; acc[11] += h2.w * w;
                        acc[12] += h3.x * w; acc[13] += h3.y * w; acc[14] += h3.z * w; acc[15] += h3.w * w;
                    }
                }
                __syncthreads();   // before restage / reduce
            }
            // partials: red[ksub][p][b]
            {
                float4* dst = (float4*)(sh + (ksub * 32 + p) * 16);
                dst[0] = make_float4(acc[0], acc[1], acc[2], acc[3]);
                dst[1] = make_float4(acc[4], acc[5], acc[6], acc[7]);
                dst[2] = make_float4(acc[8], acc[9], acc[10], acc[11]);
                dst[3] = make_float4(acc[12], acc[13], acc[14], acc[15]);
            }
            __syncthreads();
            // cell: 8 j x 16 b = 128 cells
            if (tid < 128) {
                int jl = tid >> 4, b = tid & 15;
                int jj = j0 + jl;
                float gate[4];
                #pragma unroll
                for (int g = 0; g < 4; g++) {
                    int p2 = (jl << 2) | g;
                    float s = g_xg_d[((long)b * LQ + t) * DG + g * H2 + jj];
                    #pragma unroll
                    for (int q = 0; q < 8; q++)
                        s += sh[(q * 32 + p2) * 16 + b];
                    gate[g] = s;
                }
                int ci = b * H2 + jj;
                float c = sigf(gate[1]) * g_cd[ci] + sigf(gate[0]) * tanhf(gate[2]);
                float h = sigf(gate[3]) * tanhf(c);
                g_cd[ci] = c;
                g_hdT[(long)jj * BB + b] = h;
                long base = (long)b * LQ + t;
                g_cat[base * (2 * H2) + H2 + jj] = h;
                g_x1[base * H2 + jj] = h;
            }
            gbar();
        }
    }
}

// ---------------- softmax over k with PAD mask ----------------
__global__ void k_softmax(const int* __restrict__ source) {
    int b = blockIdx.y, q = blockIdx.x;
    int k = threadIdx.x;
    long off = ((long)b * LQ + q) * LK;
    float s = g_att[off + k];
    if (source[b * LK + k] == 0) s = -INFINITY;
    __shared__ float red[64];
    red[k] = s;
    __syncthreads();
    #pragma unroll
    for (int st = 32; st > 0; st >>= 1) {
        if (k < st) red[k] = fmaxf(red[k], red[k + st]);
        __syncthreads();
    }
    float mx = red[0];
    __syncthreads();
    float e = expf(s - mx);
    red[k] = e;
    __syncthreads();
    #pragma unroll
    for (int st = 32; st > 0; st >>= 1) {
        if (k < st) red[k] += red[k + st];
        __syncthreads();
    }
    g_att[off + k] = e / red[0];
}

// ---------------- ctx = A @ V into first half of concat buffer ----------------
__global__ void k_ctx() {
    int b = blockIdx.z;
    int q0 = blockIdx.y * 16;
    int c = blockIdx.x * 128 + threadIdx.x;
    __shared__ float As[16][64];
    for (int i = threadIdx.x; i < 16 * 64; i += 128)
        As[i / 64][i & 63] = g_att[((long)b * LQ + q0 + i / 64) * LK + (i & 63)];
    __syncthreads();
    float acc[16] = {};
    for (int k = 0; k < LK; k++) {
        float v = g_Vb[((long)b * LK + k) * H2 + c];
        #pragma unroll
        for (int q = 0; q < 16; q++) acc[q] += As[q][k] * v;
    }
    #pragma unroll
    for (int q = 0; q < 16; q++)
        g_cat[((long)b * LQ + q0 + q) * (2 * H2) + c] = acc[q];
}

// ---------------- host launch ----------------
extern "C" void kernel_launch(void* const* d_in, const int* in_sizes, int n_in,
                              void* d_out, int out_size) {
    const int*   source   = (const int*)  d_in[0];
    const int*   prev     = (const int*)  d_in[1];
    const float* emb      = (const float*)d_in[2];
    const float* ef_Wih   = (const float*)d_in[3];
    const float* ef_Whh   = (const float*)d_in[4];
    const float* ef_b     = (const float*)d_in[5];
    const float* eb_Wih   = (const float*)d_in[6];
    const float* eb_Whh   = (const float*)d_in[7];
    const float* eb_b     = (const float*)d_in[8];
    const float* d_Wih    = (const float*)d_in[9];
    const float* d_Whh    = (const float*)d_in[10];
    const float* d_b      = (const float*)d_in[11];
    const float* k_W      = (const float*)d_in[12];
    const float* k_b      = (const float*)d_in[13];
    const float* v_W      = (const float*)d_in[14];
    const float* v_b      = (const float*)d_in[15];
    const float* fc1_W    = (const float*)d_in[16];
    const float* fc1_b    = (const float*)d_in[17];
    const float* fc2_W    = (const float*)d_in[18];
    const float* fc2_b    = (const float*)d_in[19];
    float* out = (float*)d_out;

    float *p_xs_src, *p_xs_prev, *p_xg_f, *p_xg_b, *p_xg_d;
    float *p_enc, *p_K, *p_V, *p_att, *p_cat, *p_x1;
    cudaGetSymbolAddress((void**)&p_xs_src, g_xs_src);
    cudaGetSymbolAddress((void**)&p_xs_prev, g_xs_prev);
    cudaGetSymbolAddress((void**)&p_xg_f, g_xg_f);
    cudaGetSymbolAddress((void**)&p_xg_b, g_xg_b);
    cudaGetSymbolAddress((void**)&p_xg_d, g_xg_d);
    cudaGetSymbolAddress((void**)&p_enc, g_enc);
    cudaGetSymbolAddress((void**)&p_K, g_Kb);
    cudaGetSymbolAddress((void**)&p_V, g_Vb);
    cudaGetSymbolAddress((void**)&p_att, g_att);
    cudaGetSymbolAddress((void**)&p_cat, g_cat);
    cudaGetSymbolAddress((void**)&p_x1, g_x1);

    // 1-3. zero + embeddings
    k_zero_states<<<(2 * BB * HH + 255) / 256, 256>>>();
    k_embed<<<(BB * LK * DD + 255) / 256, 256>>>(source, emb, p_xs_src, BB * LK);
    k_embed<<<(BB * LQ * DD + 255) / 256, 256>>>(prev, emb, p_xs_prev, BB * LQ);

    // 4-6. input pregates (tf32 mma, 128x64 tiles) — launch #6 is the ncu target
    k_tgemm<<<dim3(HG / 64, (BB * LK) / 128), 256>>>(p_xs_src, ef_Wih, ef_b, p_xg_f,
        BB * LK, HG, DD, 0);
    k_tgemm<<<dim3(HG / 64, (BB * LK) / 128), 256>>>(p_xs_src, eb_Wih, eb_b, p_xg_b,
        BB * LK, HG, DD, 0);
    k_tgemm<<<dim3(DG / 64, (BB * LQ) / 128), 256>>>(p_xs_prev, d_Wih, d_b, p_xg_d,
        BB * LQ, DG, DD, 0);

    // 7. full recurrence in ONE persistent kernel (reads Whh in native layout)
    k_recurrence<<<NBLK, NTHR>>>(ef_Whh, eb_Whh, d_Whh);

    // 8-9. K and V projections
    k_tgemm<<<dim3(H2 / 64, (BB * LK) / 128), 256>>>(p_enc, k_W, k_b, p_K,
        BB * LK, H2, H2, 0);
    k_tgemm<<<dim3(H2 / 64, (BB * LK) / 128), 256>>>(p_enc, v_W, v_b, p_V,
        BB * LK, H2, H2, 0);

    // 10. scores (fp32, Q stored in g_x1)
    k_gemm<<<dim3(1, 1, BB), dim3(16, 16)>>>(p_x1, p_K, nullptr, p_att,
        LQ, LK, H2, (long)LQ * H2, (long)LK * H2, (long)LQ * LK, 0);

    // 11. masked softmax
    k_softmax<<<dim3(LQ, BB), 64>>>(source);

    // 12. ctx = A @ V
    k_ctx<<<dim3(H2 / 128, LQ / 16, BB), 128>>>();

    // 13. fc1 with tanh (overwrites Q temp storage)
    k_tgemm<<<dim3(H2 / 64, (BB * LQ) / 128), 256>>>(p_cat, fc1_W, fc1_b, p_x1,
        BB * LQ, H2, 2 * H2, 1);

    // 14. fc2
    k_tgemm<<<dim3((VV + 63) / 64, (BB * LQ) / 128), 256>>>(p_x1, fc2_W, fc2_b, out,
        BB * LQ, VV, H2, 0);
}

// round 15
// speedup vs baseline: 1.2136x; 1.2136x over previous
#include <cuda_runtime.h>
#include <math.h>
#include <stdint.h>

// ---------------- problem constants ----------------
#define BB   16      // batch
#define LK   64      // source length
#define LQ   64      // query length
#define DD   300     // embedding dim
#define HH   512     // encoder hidden
#define H2   1024    // 2*H (decoder hidden / enc_out channels)
#define HG   2048    // 4*H  encoder gates
#define DG   4096    // 8*H  decoder gates
#define VV   10000   // vocab

#define NBLK 128
#define NTHR 256

// ---------------- scratch (device globals; no allocation) ----------------
__device__ float g_xs_src[BB * LK * DD];
__device__ float g_xs_prev[BB * LQ * DD];
__device__ float g_xg_f[BB * LK * HG];
__device__ float g_xg_b[BB * LK * HG];
__device__ float g_xg_d[BB * LQ * DG];
__device__ float g_ce[2 * BB * HH];
__device__ float g_heT[2 * HH * BB];  // enc h: (dir, j, b)
__device__ float g_cd[BB * H2];
__device__ float g_hdT[H2 * BB];      // dec h: (jj, b)
__device__ float g_enc[BB * LK * H2];
__device__ float g_Kb[BB * LK * H2];
__device__ float g_Vb[BB * LK * H2];
__device__ float g_att[BB * LQ * LK];
__device__ float g_cat[BB * LQ * 2 * H2];
__device__ float g_x1[BB * LQ * H2];

// grid barrier state (generation counter; self-resetting, replay-safe)
__device__ unsigned g_bar_cnt = 0;
__device__ unsigned g_bar_gen = 0;

__device__ __forceinline__ float sigf(float x) { return 1.f / (1.f + expf(-x)); }

__device__ __forceinline__ void gbar() {
    __syncthreads();
    if (threadIdx.x == 0) {
        volatile unsigned* genp = &g_bar_gen;
        __threadfence();
        unsigned g = *genp;
        if (atomicAdd(&g_bar_cnt, 1u) == NBLK - 1) {
            g_bar_cnt = 0;
            __threadfence();
            *genp = g + 1;
        } else {
            while (*genp == g) { }
            __threadfence();
        }
    }
    __syncthreads();
}

// ---------------- tf32 helpers (legacy mma.sync path) ----------
__device__ __forceinline__ unsigned f2tf32(float f) {
    unsigned r;
    asm("cvt.rna.tf32.f32 %0, %1;" : "=r"(r) : "f"(f));
    return r;
}

__device__ __forceinline__ void mma1688(float c[4], const unsigned a[4], const unsigned b[2]) {
    asm volatile(
        "mma.sync.aligned.m16n8k8.row.col.f32.tf32.tf32.f32 "
        "{%0,%1,%2,%3}, {%4,%5,%6,%7}, {%8,%9}, {%0,%1,%2,%3};"
        : "+f"(c[0]), "+f"(c[1]), "+f"(c[2]), "+f"(c[3])
        : "r"(a[0]), "r"(a[1]), "r"(a[2]), "r"(a[3]), "r"(b[0]), "r"(b[1]));
}

// ---------------- small utility kernels ----------------
__global__ void k_embed(const int* __restrict__ idx, const float* __restrict__ emb,
                        float* __restrict__ out, int rows) {
    int i = blockIdx.x * blockDim.x + threadIdx.x;
    if (i < rows * DD) {
        int r = i / DD, d = i - r * DD;
        out[i] = emb[(long)idx[r] * DD + d];
    }
}

// ---------------- tf32 tensor-core GEMM (R13 version: 128x128, reg prefetch) --------
// C[M,N] = A[M,K] @ W[N,K]^T (+bias)(+tanh)
// 128x128 tile, BK=32, 256 threads = 8 warps (2m x 4n), warp tile 64x32,
// mma.sync m16n8k8 tf32, fp32 accumulate. Chunk i+1 global loads prefetched
// into registers while chunk i computes.
#define ASTRIDE 36
__global__ void __launch_bounds__(256, 1)
k_tgemm(const float* __restrict__ A, const float* __restrict__ W,
        const float* __restrict__ bias, float* __restrict__ C,
        int M, int N, int K, int act) {
    __shared__ unsigned As[128 * ASTRIDE];   // [m][k], padded
    __shared__ unsigned Ws[128 * ASTRIDE];   // [n][k], padded
    const int tid = threadIdx.x;
    const int warp = tid >> 5, lane = tid & 31;
    const int wm = warp >> 2, wn = warp & 3;   // 2 x 4 warp grid
    const int gid = lane >> 2, tig = lane & 3;
    const int m0 = blockIdx.y * 128, n0 = blockIdx.x * 128;
    float acc[4][4][4] = {};   // [mi][ni][creg]

    const int nch = (K + 31) / 32;
    float4 pa[4], pw[4];

    // ---- load chunk 0 into registers ----
    {
        const int kk = 0;
        #pragma unroll
        for (int s = 0; s < 4; s++) {
            int idx = tid + s * 256;
            int row = idx >> 3, c4 = (idx & 7) * 4;
            int kb = kk + c4;
            float4 va = make_float4(0.f, 0.f, 0.f, 0.f);
            if (m0 + row < M) {
                if (kb + 3 < K) va = *(const float4*)(A + (long)(m0 + row) * K + kb);
                else {
                    const float* p = A + (long)(m0 + row) * K;
                    va.x = (kb + 0 < K) ? p[kb + 0] : 0.f;
                    va.y = (kb + 1 < K) ? p[kb + 1] : 0.f;
                    va.z = (kb + 2 < K) ? p[kb + 2] : 0.f;
                    va.w = (kb + 3 < K) ? p[kb + 3] : 0.f;
                }
            }
            pa[s] = va;
            float4 vw = make_float4(0.f, 0.f, 0.f, 0.f);
            if (n0 + row < N) {
                if (kb + 3 < K) vw = *(const float4*)(W + (long)(n0 + row) * K + kb);
                else {
                    const float* p = W + (long)(n0 + row) * K;
                    vw.x = (kb + 0 < K) ? p[kb + 0] : 0.f;
                    vw.y = (kb + 1 < K) ? p[kb + 1] : 0.f;
                    vw.z = (kb + 2 < K) ? p[kb + 2] : 0.f;
                    vw.w = (kb + 3 < K) ? p[kb + 3] : 0.f;
                }
            }
            pw[s] = vw;
        }
    }

    for (int ch = 0; ch < nch; ch++) {
        // ---- commit staged registers to smem (tf32-rounded) ----
        __syncthreads();
        #pragma unroll
        for (int s = 0; s < 4; s++) {
            int idx = tid + s * 256;
            int row = idx >> 3, c4 = (idx & 7) * 4;
            uint4 ua;
            ua.x = f2tf32(pa[s].x); ua.y = f2tf32(pa[s].y);
            ua.z = f2tf32(pa[s].z); ua.w = f2tf32(pa[s].w);
            *(uint4*)(As + row * ASTRIDE + c4) = ua;
            uint4 uw;
            uw.x = f2tf32(pw[s].x); uw.y = f2tf32(pw[s].y);
            uw.z = f2tf32(pw[s].z); uw.w = f2tf32(pw[s].w);
            *(uint4*)(Ws + row * ASTRIDE + c4) = uw;
        }
        __syncthreads();

        // ---- prefetch chunk ch+1 into registers (overlaps with mma below) ----
        if (ch + 1 < nch) {
            const int kk = (ch + 1) * 32;
            #pragma unroll
            for (int s = 0; s < 4; s++) {
                int idx = tid + s * 256;
                int row = idx >> 3, c4 = (idx & 7) * 4;
                int kb = kk + c4;
                float4 va = make_float4(0.f, 0.f, 0.f, 0.f);
                if (m0 + row < M) {
                    if (kb + 3 < K) va = *(const float4*)(A + (long)(m0 + row) * K + kb);
                    else {
                        const float* p = A + (long)(m0 + row) * K;
                        va.x = (kb + 0 < K) ? p[kb + 0] : 0.f;
                        va.y = (kb + 1 < K) ? p[kb + 1] : 0.f;
                        va.z = (kb + 2 < K) ? p[kb + 2] : 0.f;
                        va.w = (kb + 3 < K) ? p[kb + 3] : 0.f;
                    }
                }
                pa[s] = va;
                float4 vw = make_float4(0.f, 0.f, 0.f, 0.f);
                if (n0 + row < N) {
                    if (kb + 3 < K) vw = *(const float4*)(W + (long)(n0 + row) * K + kb);
                    else {
                        const float* p = W + (long)(n0 + row) * K;
                        vw.x = (kb + 0 < K) ? p[kb + 0] : 0.f;
                        vw.y = (kb + 1 < K) ? p[kb + 1] : 0.f;
                        vw.z = (kb + 2 < K) ? p[kb + 2] : 0.f;
                        vw.w = (kb + 3 < K) ? p[kb + 3] : 0.f;
                    }
                }
                pw[s] = vw;
            }
        }

        // ---- compute: 4 x K=8 mma steps ----
        #pragma unroll
        for (int ki = 0; ki < 4; ki++) {
            const int k0 = ki * 8;
            unsigned a[4][4], b[4][2];
            #pragma unroll
            for (int mi = 0; mi < 4; mi++) {
                int mr = wm * 64 + mi * 16;
                a[mi][0] = As[(mr + gid)     * ASTRIDE + k0 + tig];
                a[mi][1] = As[(mr + gid + 8) * ASTRIDE + k0 + tig];
                a[mi][2] = As[(mr + gid)     * ASTRIDE + k0 + tig + 4];
                a[mi][3] = As[(mr + gid + 8) * ASTRIDE + k0 + tig + 4];
            }
            #pragma unroll
            for (int ni = 0; ni < 4; ni++) {
                int nr = wn * 32 + ni * 8;
                b[ni][0] = Ws[(nr + gid) * ASTRIDE + k0 + tig];
                b[ni][1] = Ws[(nr + gid) * ASTRIDE + k0 + tig + 4];
            }
            #pragma unroll
            for (int mi = 0; mi < 4; mi++)
                #pragma unroll
                for (int ni = 0; ni < 4; ni++)
                    mma1688(acc[mi][ni], a[mi], b[ni]);
        }
    }

    // epilogue
    #pragma unroll
    for (int mi = 0; mi < 4; mi++) {
        int m1 = m0 + wm * 64 + mi * 16 + gid;
        int m2 = m1 + 8;
        #pragma unroll
        for (int ni = 0; ni < 4; ni++) {
            int nc = n0 + wn * 32 + ni * 8 + 2 * tig;
            float b0 = 0.f, b1 = 0.f;
            if (bias) {
                if (nc < N)     b0 = bias[nc];
                if (nc + 1 < N) b1 = bias[nc + 1];
            }
            float v0 = acc[mi][ni][0] + b0;
            float v1 = acc[mi][ni][1] + b1;
            float v2 = acc[mi][ni][2] + b0;
            float v3 = acc[mi][ni][3] + b1;
            if (act == 1) { v0 = tanhf(v0); v1 = tanhf(v1); v2 = tanhf(v2); v3 = tanhf(v3); }
            if (m1 < M) {
                if (nc < N)     C[(long)m1 * N + nc]     = v0;
                if (nc + 1 < N) C[(long)m1 * N + nc + 1] = v1;
            }
            if (m2 < M) {
                if (nc < N)     C[(long)m2 * N + nc]     = v2;
                if (nc + 1 < N) C[(long)m2 * N + nc + 1] = v3;
            }
        }
    }
}

// ---------------- small batched GEMM for attention scores (fp32) ----------------
__global__ void k_gemm(const float* __restrict__ A, const float* __restrict__ W,
                       const float* __restrict__ bias, float* __restrict__ C,
                       int M, int N, int K, long sA, long sW, long sC, int act) {
    A += (long)blockIdx.z * sA;
    W += (long)blockIdx.z * sW;
    C += (long)blockIdx.z * sC;
    __shared__ float As[16][68];
    __shared__ float Ws[16][68];
    int m0 = blockIdx.y * 64, n0 = blockIdx.x * 64;
    int tx = threadIdx.x, ty = threadIdx.y;
    int tid = ty * 16 + tx;
    float acc[4][4] = {};
    for (int kk = 0; kk < K; kk += 16) {
        #pragma unroll
        for (int s = 0; s < 4; s++) {
            int e = tid + s * 256;
            int mm = e >> 4, k = e & 15;
            float va = 0.f, vw = 0.f;
            if (m0 + mm < M && kk + k < K) va = A[(long)(m0 + mm) * K + kk + k];
            if (n0 + mm < N && kk + k < K) vw = W[(long)(n0 + mm) * K + kk + k];
            As[k][mm] = va;
            Ws[k][mm] = vw;
        }
        __syncthreads();
        #pragma unroll
        for (int k = 0; k < 16; k++) {
            float a[4], w[4];
            #pragma unroll
            for (int i = 0; i < 4; i++) a[i] = As[k][ty * 4 + i];
            #pragma unroll
            for (int j = 0; j < 4; j++) w[j] = Ws[k][tx * 4 + j];
            #pragma unroll
            for (int i = 0; i < 4; i++)
                #pragma unroll
                for (int j = 0; j < 4; j++) acc[i][j] += a[i] * w[j];
        }
        __syncthreads();
    }
    #pragma unroll
    for (int i = 0; i < 4; i++) {
        int m = m0 + ty * 4 + i;
        if (m >= M) continue;
        #pragma unroll
        for (int j = 0; j < 4; j++) {
            int n = n0 + tx * 4 + j;
            if (n >= N) continue;
            float v = acc[i][j];
            if (bias) v += bias[n];
            if (act == 1) v = tanhf(v);
            C[(long)m * N + n] = v;
        }
    }
}

// ---------------- persistent recurrence kernel (1 grid barrier per step) ----------
// Self-zeroing (no separate zero launch). Each block owns 8 hidden units j and
// computes all four gate rows, k-split 8-way within block, smem-reduced, cell in-block.
__global__ void __launch_bounds__(NTHR, 1)
k_recurrence(const float* __restrict__ efW, const float* __restrict__ ebW,
             const float* __restrict__ dW) {
    __shared__ float sh[8192];          // 32KB: h stage, then partial-reduce
    float4* shv = (float4*)sh;
    const int tid = threadIdx.x;
    const int p = tid & 31;             // (jloc, gate): jloc = p>>2, g = p&3
    const int gg = p & 3, jloc = p >> 2;
    const int ksub = tid >> 5;          // 0..7 — warp-uniform k-range

    // ---- zero encoder state (replaces k_zero_states launch) ----
    {
        int gt = blockIdx.x * NTHR + tid;
        if (gt < 2 * BB * HH) { g_ce[gt] = 0.f; g_heT[gt] = 0.f; }
    }
    gbar();

    // ===================== encoder =====================
    {
        const int dir = blockIdx.x >> 6;        // 0..1
        const int j0 = (blockIdx.x & 63) * 8;   // 64 blocks per dir x 8 j
        const int j = j0 + jloc;
        const float* W = (dir ? ebW : efW) + (long)(gg * HH + j) * HH;
        const float* hT = g_heT + dir * HH * BB;
        const float* xg = dir ? g_xg_b : g_xg_f;
        const float* Wp = W + ksub * 64;

        for (int t = 0; t < LK; t++) {
            // stage h: 512 j x 16 b = 8192 floats
            #pragma unroll
            for (int i = 0; i < 8; i++)
                shv[tid + i * NTHR] = ((const float4*)hT)[tid + i * NTHR];
            __syncthreads();

            float acc[16] = {};
            float4 w0 = *(const float4*)(Wp);
            float4 w1 = *(const float4*)(Wp + 4);
            const float4* sh4 = (const float4*)sh;
            #pragma unroll
            for (int kq = 0; kq < 16; kq++) {
                float4 wc = (kq & 1) ? w1 : w0;
                if (kq + 2 < 16) {
                    float4 wn = *(const float4*)(Wp + (kq + 2) * 4);
                    if (kq & 1) w1 = wn; else w0 = wn;
                }
                int kb = ksub * 64 + kq * 4;
                #pragma unroll
                for (int i = 0; i < 4; i++) {
                    float w = (&wc.x)[i];
                    float4 h0 = sh4[(kb + i) * 4 + 0];
                    float4 h1 = sh4[(kb + i) * 4 + 1];
                    float4 h2 = sh4[(kb + i) * 4 + 2];
                    float4 h3 = sh4[(kb + i) * 4 + 3];
                    acc[0]  += h0.x * w; acc[1]  += h0.y * w; acc[2]  += h0.z * w; acc[3]  += h0.w * w;
                    acc[4]  += h1.x * w; acc[5]  += h1.y * w; acc[6]  += h1.z * w; acc[7]  += h1.w * w;
                    acc[8]  += h2.x * w; acc[9]  += h2.y * w; acc[10] += h2.z * w; acc[11] += h2.w * w;
                    acc[12] += h3.x * w; acc[13] += h3.y * w; acc[14] += h3.z * w; acc[15] += h3.w * w;
                }
            }
            __syncthreads();   // done reading h stage
            // partials: red[ksub][p][b]
            {
                float4* dst = (float4*)(sh + (ksub * 32 + p) * 16);
                dst[0] = make_float4(acc[0], acc[1], acc[2], acc[3]);
                dst[1] = make_float4(acc[4], acc[5], acc[6], acc[7]);
                dst[2] = make_float4(acc[8], acc[9], acc[10], acc[11]);
                dst[3] = make_float4(acc[12], acc[13], acc[14], acc[15]);
            }
            __syncthreads();
            // cell: 8 j x 16 b = 128 cells
            if (tid < 128) {
                int jl = tid >> 4, b = tid & 15;
                int jj = j0 + jl;
                int tt = dir ? (LK - 1 - t) : t;
                float gate[4];
                #pragma unroll
                for (int g = 0; g < 4; g++) {
                    int p2 = (jl << 2) | g;
                    float s = xg[((long)b * LK + tt) * HG + g * HH + jj];
                    #pragma unroll
                    for (int q = 0; q < 8; q++)
                        s += sh[(q * 32 + p2) * 16 + b];
                    gate[g] = s;
                }
                int si = dir * BB * HH + b * HH + jj;
                float c = sigf(gate[1]) * g_ce[si] + sigf(gate[0]) * tanhf(gate[2]);
                float h = sigf(gate[3]) * tanhf(c);
                g_ce[si] = c;
                g_heT[(long)dir * HH * BB + (long)jj * BB + b] = h;
                g_enc[((long)b * LK + tt) * H2 + dir * HH + jj] = h;
            }
            gbar();
        }
    }

    // ===================== decoder init =====================
    {
        int gt = blockIdx.x * NTHR + tid;
        if (gt < BB * H2) {
            int b = gt >> 10, jj = gt & (H2 - 1);
            int dir = jj & 1, j = jj >> 1;
            g_hdT[(long)jj * BB + b] = g_heT[(long)dir * HH * BB + (long)j * BB + b];
            g_cd[gt] = g_ce[dir * BB * HH + b * HH + j];
        }
    }
    gbar();

    // ===================== decoder =====================
    {
        const int j0 = blockIdx.x * 8;          // 128 blocks x 8 j = 1024
        const int j = j0 + jloc;
        const float* W = dW + (long)(gg * H2 + j) * H2;

        for (int t = 0; t < LQ; t++) {
            float acc[16] = {};
            #pragma unroll
            for (int half = 0; half < 2; half++) {
                const float4* hsrc = (const float4*)(g_hdT + half * 512 * BB);
                #pragma unroll
                for (int i = 0; i < 8; i++)
                    shv[tid + i * NTHR] = hsrc[tid + i * NTHR];
                __syncthreads();

                const float* Wp = W + half * 512 + ksub * 64;
                float4 w0 = *(const float4*)(Wp);
                float4 w1 = *(const float4*)(Wp + 4);
                const float4* sh4 = (const float4*)sh;
                #pragma unroll
                for (int kq = 0; kq < 16; kq++) {
                    float4 wc = (kq & 1) ? w1 : w0;
                    if (kq + 2 < 16) {
                        float4 wn = *(const float4*)(Wp + (kq + 2) * 4);
                        if (kq & 1) w1 = wn; else w0 = wn;
                    }
                    int kb = ksub * 64 + kq * 4;
                    #pragma unroll
                    for (int i = 0; i < 4; i++) {
                        float w = (&wc.x)[i];
                        float4 h0 = sh4[(kb + i) * 4 + 0];
                        float4 h1 = sh4[(kb + i) * 4 + 1];
                        float4 h2 = sh4[(kb + i) * 4 + 2];
                        float4 h3 = sh4[(kb + i) * 4 + 3];
                        acc[0]  += h0.x * w; acc[1]  += h0.y * w; acc[2]  += h0.z * w; acc[3]  += h0.w * w;
                        acc[4]  += h1.x * w; acc[5]  += h1.y * w; acc[6]  += h1.z * w; acc[7]  += h1.w * w;
                        acc[8]  += h2.x * w; acc[9]  += h2.y * w; acc[10] += h2.z * w; acc[11] += h2.w * w;
                        acc[12] += h3.x * w; acc[13] += h3.y * w; acc[14] += h3.z * w; acc[15] += h3.w * w;
                    }
                }
                __syncthreads();   // before restage / reduce
            }
            // partials: red[ksub][p][b]
            {
                float4* dst = (float4*)(sh + (ksub * 32 + p) * 16);
                dst[0] = make_float4(acc[0], acc[1], acc[2], acc[3]);
                dst[1] = make_float4(acc[4], acc[5], acc[6], acc[7]);
                dst[2] = make_float4(acc[8], acc[9], acc[10], acc[11]);
                dst[3] = make_float4(acc[12], acc[13], acc[14], acc[15]);
            }
            __syncthreads();
            // cell: 8 j x 16 b = 128 cells
            if (tid < 128) {
                int jl = tid >> 4, b = tid & 15;
                int jj = j0 + jl;
                float gate[4];
                #pragma unroll
                for (int g = 0; g < 4; g++) {
                    int p2 = (jl << 2) | g;
                    float s = g_xg_d[((long)b * LQ + t) * DG + g * H2 + jj];
                    #pragma unroll
                    for (int q = 0; q < 8; q++)
                        s += sh[(q * 32 + p2) * 16 + b];
                    gate[g] = s;
                }
                int ci = b * H2 + jj;
                float c = sigf(gate[1]) * g_cd[ci] + sigf(gate[0]) * tanhf(gate[2]);
                float h = sigf(gate[3]) * tanhf(c);
                g_cd[ci] = c;
                g_hdT[(long)jj * BB + b] = h;
                long base = (long)b * LQ + t;
                g_cat[base * (2 * H2) + H2 + jj] = h;
                g_x1[base * H2 + jj] = h;
            }
            gbar();
        }
    }
}

// ---------------- softmax over k with PAD mask ----------------
__global__ void k_softmax(const int* __restrict__ source) {
    int b = blockIdx.y, q = blockIdx.x;
    int k = threadIdx.x;
    long off = ((long)b * LQ + q) * LK;
    float s = g_att[off + k];
    if (source[b * LK + k] == 0) s = -INFINITY;
    __shared__ float red[64];
    red[k] = s;
    __syncthreads();
    #pragma unroll
    for (int st = 32; st > 0; st >>= 1) {
        if (k < st) red[k] = fmaxf(red[k], red[k + st]);
        __syncthreads();
    }
    float mx = red[0];
    __syncthreads();
    float e = expf(s - mx);
    red[k] = e;
    __syncthreads();
    #pragma unroll
    for (int st = 32; st > 0; st >>= 1) {
        if (k < st) red[k] += red[k + st];
        __syncthreads();
    }
    g_att[off + k] = e / red[0];
}

// ---------------- ctx = A @ V into first half of concat buffer ----------------
__global__ void k_ctx() {
    int b = blockIdx.z;
    int q0 = blockIdx.y * 16;
    int c = blockIdx.x * 128 + threadIdx.x;
    __shared__ float As[16][64];
    for (int i = threadIdx.x; i < 16 * 64; i += 128)
        As[i / 64][i & 63] = g_att[((long)b * LQ + q0 + i / 64) * LK + (i & 63)];
    __syncthreads();
    float acc[16] = {};
    for (int k = 0; k < LK; k++) {
        float v = g_Vb[((long)b * LK + k) * H2 + c];
        #pragma unroll
        for (int q = 0; q < 16; q++) acc[q] += As[q][k] * v;
    }
    #pragma unroll
    for (int q = 0; q < 16; q++)
        g_cat[((long)b * LQ + q0 + q) * (2 * H2) + c] = acc[q];
}

// ---------------- host launch ----------------
extern "C" void kernel_launch(void* const* d_in, const int* in_sizes, int n_in,
                              void* d_out, int out_size) {
    const int*   source   = (const int*)  d_in[0];
    const int*   prev     = (const int*)  d_in[1];
    const float* emb      = (const float*)d_in[2];
    const float* ef_Wih   = (const float*)d_in[3];
    const float* ef_Whh   = (const float*)d_in[4];
    const float* ef_b     = (const float*)d_in[5];
    const float* eb_Wih   = (const float*)d_in[6];
    const float* eb_Whh   = (const float*)d_in[7];
    const float* eb_b     = (const float*)d_in[8];
    const float* d_Wih    = (const float*)d_in[9];
    const float* d_Whh    = (const float*)d_in[10];
    const float* d_b      = (const float*)d_in[11];
    const float* k_W      = (const float*)d_in[12];
    const float* k_b      = (const float*)d_in[13];
    const float* v_W      = (const float*)d_in[14];
    const float* v_b      = (const float*)d_in[15];
    const float* fc1_W    = (const float*)d_in[16];
    const float* fc1_b    = (const float*)d_in[17];
    const float* fc2_W    = (const float*)d_in[18];
    const float* fc2_b    = (const float*)d_in[19];
    float* out = (float*)d_out;

    float *p_xs_src, *p_xs_prev, *p_xg_f, *p_xg_b, *p_xg_d;
    float *p_enc, *p_K, *p_V, *p_att, *p_cat, *p_x1;
    cudaGetSymbolAddress((void**)&p_xs_src, g_xs_src);
    cudaGetSymbolAddress((void**)&p_xs_prev, g_xs_prev);
    cudaGetSymbolAddress((void**)&p_xg_f, g_xg_f);
    cudaGetSymbolAddress((void**)&p_xg_b, g_xg_b);
    cudaGetSymbolAddress((void**)&p_xg_d, g_xg_d);
    cudaGetSymbolAddress((void**)&p_enc, g_enc);
    cudaGetSymbolAddress((void**)&p_K, g_Kb);
    cudaGetSymbolAddress((void**)&p_V, g_Vb);
    cudaGetSymbolAddress((void**)&p_att, g_att);
    cudaGetSymbolAddress((void**)&p_cat, g_cat);
    cudaGetSymbolAddress((void**)&p_x1, g_x1);

    // 0-1. embeddings
    k_embed<<<(BB * LK * DD + 255) / 256, 256>>>(source, emb, p_xs_src, BB * LK);
    k_embed<<<(BB * LQ * DD + 255) / 256, 256>>>(prev, emb, p_xs_prev, BB * LQ);

    // 2-4. input pregates (tf32 mma, 128x128 tiles)
    k_tgemm<<<dim3(HG / 128, (BB * LK) / 128), 256>>>(p_xs_src, ef_Wih, ef_b, p_xg_f,
        BB * LK, HG, DD, 0);
    k_tgemm<<<dim3(HG / 128, (BB * LK) / 128), 256>>>(p_xs_src, eb_Wih, eb_b, p_xg_b,
        BB * LK, HG, DD, 0);
    k_tgemm<<<dim3(DG / 128, (BB * LQ) / 128), 256>>>(p_xs_prev, d_Wih, d_b, p_xg_d,
        BB * LQ, DG, DD, 0);

    // 5. full recurrence (self-zeroing) — this is launch index 5 = the ncu target
    k_recurrence<<<NBLK, NTHR>>>(ef_Whh, eb_Whh, d_Whh);

    // 6-7. K and V projections
    k_tgemm<<<dim3(H2 / 128, (BB * LK) / 128), 256>>>(p_enc, k_W, k_b, p_K,
        BB * LK, H2, H2, 0);
    k_tgemm<<<dim3(H2 / 128, (BB * LK) / 128), 256>>>(p_enc, v_W, v_b, p_V,
        BB * LK, H2, H2, 0);

    // 8. scores (fp32, Q stored in g_x1)
    k_gemm<<<dim3(1, 1, BB), dim3(16, 16)>>>(p_x1, p_K, nullptr, p_att,
        LQ, LK, H2, (long)LQ * H2, (long)LK * H2, (long)LQ * LK, 0);

    // 9. masked softmax
    k_softmax<<<dim3(LQ, BB), 64>>>(source);

    // 10. ctx = A @ V
    k_ctx<<<dim3(H2 / 128, LQ / 16, BB), 128>>>();

    // 11. fc1 with tanh (overwrites Q temp storage)
    k_tgemm<<<dim3(H2 / 128, (BB * LQ) / 128), 256>>>(p_cat, fc1_W, fc1_b, p_x1,
        BB * LQ, H2, 2 * H2, 1);

    // 12. fc2
    k_tgemm<<<dim3((VV + 127) / 128, (BB * LQ) / 128), 256>>>(p_x1, fc2_W, fc2_b, out,
        BB * LQ, VV, H2, 0);
}

// round 16
// speedup vs baseline: 1.4898x; 1.2276x over previous
#include <cuda_runtime.h>
#include <math.h>
#include <stdint.h>

// ---------------- problem constants ----------------
#define BB   16      // batch
#define LK   64      // source length
#define LQ   64      // query length
#define DD   300     // embedding dim
#define HH   512     // encoder hidden
#define H2   1024    // 2*H (decoder hidden / enc_out channels)
#define HG   2048    // 4*H  encoder gates
#define DG   4096    // 8*H  decoder gates
#define VV   10000   // vocab

#define NBLK 128
#define NTHR 256

// smem strides (u32 units), chosen so stride % 32 == 4 -> conflict-free frags
#define SHD  516     // dec h row stride: 1024/2 + 4
#define SHE  260     // enc h row stride: 512/2 + 4

// ---------------- scratch (device globals; no allocation) ----------------
__device__ float g_xs_src[BB * LK * DD];
__device__ float g_xs_prev[BB * LQ * DD];
__device__ float g_xg_f[BB * LK * HG];
__device__ float g_xg_b[BB * LK * HG];
__device__ float g_xg_d[BB * LQ * DG];
__device__ float g_ce[2 * BB * HH];
__device__ float g_he[2 * BB * HH];   // enc h: (dir, b, j) natural
__device__ float g_cd[BB * H2];
__device__ float g_hd[BB * H2];       // dec h: (b, jj) natural
__device__ float g_enc[BB * LK * H2];
__device__ float g_Kb[BB * LK * H2];
__device__ float g_Vb[BB * LK * H2];
__device__ float g_att[BB * LQ * LK];
__device__ float g_cat[BB * LQ * 2 * H2];
__device__ float g_x1[BB * LQ * H2];

// bf16 hi/lo split recurrent weights (u32 = 2 packed bf16, k-major pairs)
__device__ unsigned g_eWhi[2 * HG * HH / 2];
__device__ unsigned g_eWlo[2 * HG * HH / 2];
__device__ unsigned g_dWhi[DG * H2 / 2];
__device__ unsigned g_dWlo[DG * H2 / 2];

// grid barrier state (generation counter; self-resetting, replay-safe)
__device__ unsigned g_bar_cnt = 0;
__device__ unsigned g_bar_gen = 0;

__device__ __forceinline__ float sigf(float x) { return 1.f / (1.f + expf(-x)); }

__device__ __forceinline__ void gbar() {
    __syncthreads();
    if (threadIdx.x == 0) {
        volatile unsigned* genp = &g_bar_gen;
        __threadfence();
        unsigned g = *genp;
        if (atomicAdd(&g_bar_cnt, 1u) == NBLK - 1) {
            g_bar_cnt = 0;
            __threadfence();
            *genp = g + 1;
        } else {
            while (*genp == g) { }
            __threadfence();
        }
    }
    __syncthreads();
}

// ---------------- mma helpers ----------------
__device__ __forceinline__ unsigned f2tf32(float f) {
    unsigned r;
    asm("cvt.rna.tf32.f32 %0, %1;" : "=r"(r) : "f"(f));
    return r;
}

__device__ __forceinline__ void mma1688(float c[4], const unsigned a[4], const unsigned b[2]) {
    asm volatile(
        "mma.sync.aligned.m16n8k8.row.col.f32.tf32.tf32.f32 "
        "{%0,%1,%2,%3}, {%4,%5,%6,%7}, {%8,%9}, {%0,%1,%2,%3};"
        : "+f"(c[0]), "+f"(c[1]), "+f"(c[2]), "+f"(c[3])
        : "r"(a[0]), "r"(a[1]), "r"(a[2]), "r"(a[3]), "r"(b[0]), "r"(b[1]));
}

// bf16 m16n8k16
__device__ __forceinline__ void mma16816(float c[4], const unsigned a[4], const unsigned b[2]) {
    asm volatile(
        "mma.sync.aligned.m16n8k16.row.col.f32.bf16.bf16.f32 "
        "{%0,%1,%2,%3}, {%4,%5,%6,%7}, {%8,%9}, {%0,%1,%2,%3};"
        : "+f"(c[0]), "+f"(c[1]), "+f"(c[2]), "+f"(c[3])
        : "r"(a[0]), "r"(a[1]), "r"(a[2]), "r"(a[3]), "r"(b[0]), "r"(b[1]));
}

// pack bf16(lo half = x, hi half = y)
__device__ __forceinline__ unsigned packbf(float x, float y) {
    unsigned r;
    asm("cvt.rn.bf16x2.f32 %0, %1, %2;" : "=r"(r) : "f"(y), "f"(x));
    return r;
}

// split float4 -> hi bf16x2 pair + lo bf16x2 pair
__device__ __forceinline__ void bf16split4(float4 v, unsigned& hi0, unsigned& hi1,
                                           unsigned& lo0, unsigned& lo1) {
    hi0 = packbf(v.x, v.y);
    hi1 = packbf(v.z, v.w);
    float h0 = __uint_as_float(hi0 << 16), h1 = __uint_as_float(hi0 & 0xffff0000u);
    float h2 = __uint_as_float(hi1 << 16), h3 = __uint_as_float(hi1 & 0xffff0000u);
    lo0 = packbf(v.x - h0, v.y - h1);
    lo1 = packbf(v.z - h2, v.w - h3);
}

// ---------------- small utility kernels ----------------
__global__ void k_embed(const int* __restrict__ idx, const float* __restrict__ emb,
                        float* __restrict__ out, int rows) {
    int i = blockIdx.x * blockDim.x + threadIdx.x;
    if (i < rows * DD) {
        int r = i / DD, d = i - r * DD;
        out[i] = emb[(long)idx[r] * DD + d];
    }
}

// split fp32 weights into bf16 hi/lo packed pairs
__global__ void k_wsplit(const float* __restrict__ src, unsigned* __restrict__ hi,
                         unsigned* __restrict__ lo, int n2) {
    int i = blockIdx.x * blockDim.x + threadIdx.x;
    if (i < n2) {
        float2 v = ((const float2*)src)[i];
        unsigned h = packbf(v.x, v.y);
        float h0 = __uint_as_float(h << 16), h1 = __uint_as_float(h & 0xffff0000u);
        hi[i] = h;
        lo[i] = packbf(v.x - h0, v.y - h1);
    }
}

// ---------------- tf32 tensor-core GEMM (R13 version: 128x128, reg prefetch) --------
#define ASTRIDE 36
__global__ void __launch_bounds__(256, 1)
k_tgemm(const float* __restrict__ A, const float* __restrict__ W,
        const float* __restrict__ bias, float* __restrict__ C,
        int M, int N, int K, int act) {
    __shared__ unsigned As[128 * ASTRIDE];
    __shared__ unsigned Ws[128 * ASTRIDE];
    const int tid = threadIdx.x;
    const int warp = tid >> 5, lane = tid & 31;
    const int wm = warp >> 2, wn = warp & 3;
    const int gid = lane >> 2, tig = lane & 3;
    const int m0 = blockIdx.y * 128, n0 = blockIdx.x * 128;
    float acc[4][4][4] = {};
    const int nch = (K + 31) / 32;
    float4 pa[4], pw[4];

    {
        #pragma unroll
        for (int s = 0; s < 4; s++) {
            int idx = tid + s * 256;
            int row = idx >> 3, c4 = (idx & 7) * 4;
            int kb = c4;
            float4 va = make_float4(0.f, 0.f, 0.f, 0.f);
            if (m0 + row < M) {
                if (kb + 3 < K) va = *(const float4*)(A + (long)(m0 + row) * K + kb);
                else {
                    const float* p = A + (long)(m0 + row) * K;
                    va.x = (kb + 0 < K) ? p[kb + 0] : 0.f;
                    va.y = (kb + 1 < K) ? p[kb + 1] : 0.f;
                    va.z = (kb + 2 < K) ? p[kb + 2] : 0.f;
                    va.w = (kb + 3 < K) ? p[kb + 3] : 0.f;
                }
            }
            pa[s] = va;
            float4 vw = make_float4(0.f, 0.f, 0.f, 0.f);
            if (n0 + row < N) {
                if (kb + 3 < K) vw = *(const float4*)(W + (long)(n0 + row) * K + kb);
                else {
                    const float* p = W + (long)(n0 + row) * K;
                    vw.x = (kb + 0 < K) ? p[kb + 0] : 0.f;
                    vw.y = (kb + 1 < K) ? p[kb + 1] : 0.f;
                    vw.z = (kb + 2 < K) ? p[kb + 2] : 0.f;
                    vw.w = (kb + 3 < K) ? p[kb + 3] : 0.f;
                }
            }
            pw[s] = vw;
        }
    }

    for (int ch = 0; ch < nch; ch++) {
        __syncthreads();
        #pragma unroll
        for (int s = 0; s < 4; s++) {
            int idx = tid + s * 256;
            int row = idx >> 3, c4 = (idx & 7) * 4;
            uint4 ua;
            ua.x = f2tf32(pa[s].x); ua.y = f2tf32(pa[s].y);
            ua.z = f2tf32(pa[s].z); ua.w = f2tf32(pa[s].w);
            *(uint4*)(As + row * ASTRIDE + c4) = ua;
            uint4 uw;
            uw.x = f2tf32(pw[s].x); uw.y = f2tf32(pw[s].y);
            uw.z = f2tf32(pw[s].z); uw.w = f2tf32(pw[s].w);
            *(uint4*)(Ws + row * ASTRIDE + c4) = uw;
        }
        __syncthreads();

        if (ch + 1 < nch) {
            const int kk = (ch + 1) * 32;
            #pragma unroll
            for (int s = 0; s < 4; s++) {
                int idx = tid + s * 256;
                int row = idx >> 3, c4 = (idx & 7) * 4;
                int kb = kk + c4;
                float4 va = make_float4(0.f, 0.f, 0.f, 0.f);
                if (m0 + row < M) {
                    if (kb + 3 < K) va = *(const float4*)(A + (long)(m0 + row) * K + kb);
                    else {
                        const float* p = A + (long)(m0 + row) * K;
                        va.x = (kb + 0 < K) ? p[kb + 0] : 0.f;
                        va.y = (kb + 1 < K) ? p[kb + 1] : 0.f;
                        va.z = (kb + 2 < K) ? p[kb + 2] : 0.f;
                        va.w = (kb + 3 < K) ? p[kb + 3] : 0.f;
                    }
                }
                pa[s] = va;
                float4 vw = make_float4(0.f, 0.f, 0.f, 0.f);
                if (n0 + row < N) {
                    if (kb + 3 < K) vw = *(const float4*)(W + (long)(n0 + row) * K + kb);
                    else {
                        const float* p = W + (long)(n0 + row) * K;
                        vw.x = (kb + 0 < K) ? p[kb + 0] : 0.f;
                        vw.y = (kb + 1 < K) ? p[kb + 1] : 0.f;
                        vw.z = (kb + 2 < K) ? p[kb + 2] : 0.f;
                        vw.w = (kb + 3 < K) ? p[kb + 3] : 0.f;
                    }
                }
                pw[s] = vw;
            }
        }

        #pragma unroll
        for (int ki = 0; ki < 4; ki++) {
            const int k0 = ki * 8;
            unsigned a[4][4], b[4][2];
            #pragma unroll
            for (int mi = 0; mi < 4; mi++) {
                int mr = wm * 64 + mi * 16;
                a[mi][0] = As[(mr + gid)     * ASTRIDE + k0 + tig];
                a[mi][1] = As[(mr + gid + 8) * ASTRIDE + k0 + tig];
                a[mi][2] = As[(mr + gid)     * ASTRIDE + k0 + tig + 4];
                a[mi][3] = As[(mr + gid + 8) * ASTRIDE + k0 + tig + 4];
            }
            #pragma unroll
            for (int ni = 0; ni < 4; ni++) {
                int nr = wn * 32 + ni * 8;
                b[ni][0] = Ws[(nr + gid) * ASTRIDE + k0 + tig];
                b[ni][1] = Ws[(nr + gid) * ASTRIDE + k0 + tig + 4];
            }
            #pragma unroll
            for (int mi = 0; mi < 4; mi++)
                #pragma unroll
                for (int ni = 0; ni < 4; ni++)
                    mma1688(acc[mi][ni], a[mi], b[ni]);
        }
    }

    #pragma unroll
    for (int mi = 0; mi < 4; mi++) {
        int m1 = m0 + wm * 64 + mi * 16 + gid;
        int m2 = m1 + 8;
        #pragma unroll
        for (int ni = 0; ni < 4; ni++) {
            int nc = n0 + wn * 32 + ni * 8 + 2 * tig;
            float b0 = 0.f, b1 = 0.f;
            if (bias) {
                if (nc < N)     b0 = bias[nc];
                if (nc + 1 < N) b1 = bias[nc + 1];
            }
            float v0 = acc[mi][ni][0] + b0;
            float v1 = acc[mi][ni][1] + b1;
            float v2 = acc[mi][ni][2] + b0;
            float v3 = acc[mi][ni][3] + b1;
            if (act == 1) { v0 = tanhf(v0); v1 = tanhf(v1); v2 = tanhf(v2); v3 = tanhf(v3); }
            if (m1 < M) {
                if (nc < N)     C[(long)m1 * N + nc]     = v0;
                if (nc + 1 < N) C[(long)m1 * N + nc + 1] = v1;
            }
            if (m2 < M) {
                if (nc < N)     C[(long)m2 * N + nc]     = v2;
                if (nc + 1 < N) C[(long)m2 * N + nc + 1] = v3;
            }
        }
    }
}

// ---------------- small batched GEMM for attention scores (fp32) ----------------
__global__ void k_gemm(const float* __restrict__ A, const float* __restrict__ W,
                       const float* __restrict__ bias, float* __restrict__ C,
                       int M, int N, int K, long sA, long sW, long sC, int act) {
    A += (long)blockIdx.z * sA;
    W += (long)blockIdx.z * sW;
    C += (long)blockIdx.z * sC;
    __shared__ float As[16][68];
    __shared__ float Ws[16][68];
    int m0 = blockIdx.y * 64, n0 = blockIdx.x * 64;
    int tx = threadIdx.x, ty = threadIdx.y;
    int tid = ty * 16 + tx;
    float acc[4][4] = {};
    for (int kk = 0; kk < K; kk += 16) {
        #pragma unroll
        for (int s = 0; s < 4; s++) {
            int e = tid + s * 256;
            int mm = e >> 4, k = e & 15;
            float va = 0.f, vw = 0.f;
            if (m0 + mm < M && kk + k < K) va = A[(long)(m0 + mm) * K + kk + k];
            if (n0 + mm < N && kk + k < K) vw = W[(long)(n0 + mm) * K + kk + k];
            As[k][mm] = va;
            Ws[k][mm] = vw;
        }
        __syncthreads();
        #pragma unroll
        for (int k = 0; k < 16; k++) {
            float a[4], w[4];
            #pragma unroll
            for (int i = 0; i < 4; i++) a[i] = As[k][ty * 4 + i];
            #pragma unroll
            for (int j = 0; j < 4; j++) w[j] = Ws[k][tx * 4 + j];
            #pragma unroll
            for (int i = 0; i < 4; i++)
                #pragma unroll
                for (int j = 0; j < 4; j++) acc[i][j] += a[i] * w[j];
        }
        __syncthreads();
    }
    #pragma unroll
    for (int i = 0; i < 4; i++) {
        int m = m0 + ty * 4 + i;
        if (m >= M) continue;
        #pragma unroll
        for (int j = 0; j < 4; j++) {
            int n = n0 + tx * 4 + j;
            if (n >= N) continue;
            float v = acc[i][j];
            if (bias) v += bias[n];
            if (act == 1) v = tanhf(v);
            C[(long)m * N + n] = v;
        }
    }
}

// ---------------- persistent recurrence: bf16-split tensor-core matvec ----------
// Block owns 8 hidden units j (32 gate rows). Per step: stage h (bf16 hi/lo) to
// smem, 8 warps k-split, 3-term mma per tile, smem reduce, cell in-block, 1 gbar.
__global__ void __launch_bounds__(NTHR, 1)
k_recurrence() {
    extern __shared__ unsigned dsh[];
    unsigned* hh32 = dsh;                 // h hi: rows x SHD/SHE u32
    unsigned* hl32 = dsh + 16 * SHD;      // h lo
    float* red = (float*)(dsh + 2 * 16 * SHD);   // [8][32][16]

    const int tid = threadIdx.x;
    const int lane = tid & 31;
    const int ksub = tid >> 5;            // warp id = k-slice
    const int gid = lane >> 2, tig = lane & 3;

    // ---- zero encoder state ----
    {
        int gt = blockIdx.x * NTHR + tid;
        if (gt < 2 * BB * HH) { g_ce[gt] = 0.f; g_he[gt] = 0.f; }
    }
    gbar();

    // ===================== encoder =====================
    {
        const int dir = blockIdx.x >> 6;
        const int j0 = (blockIdx.x & 63) * 8;
        const unsigned* Whi = g_eWhi + (long)dir * (HG * HH / 2);
        const unsigned* Wlo = g_eWlo + (long)dir * (HG * HH / 2);
        const float* xg = dir ? g_xg_b : g_xg_f;
        const float* hsrc = g_he + dir * BB * HH;

        // per-thread A row indices: mma rows gid, gid+8, gid+16, gid+24
        long pWr[4];
        #pragma unroll
        for (int i = 0; i < 4; i++) {
            int r = gid + i * 8;
            int g = r >> 3, jl = r & 7;
            pWr[i] = (long)(g * HH + j0 + jl) * (HH / 2);
        }

        for (int t = 0; t < LK; t++) {
            // stage h: 16 x 512 floats -> bf16 hi/lo
            #pragma unroll
            for (int i = 0; i < 8; i++) {
                int idx = tid + i * NTHR;          // 0..2047 float4 index
                int b = idx >> 7, k4 = idx & 127;
                float4 v = ((const float4*)hsrc)[idx];
                unsigned h0, h1, l0, l1;
                bf16split4(v, h0, h1, l0, l1);
                hh32[b * SHE + k4 * 2]     = h0;
                hh32[b * SHE + k4 * 2 + 1] = h1;
                hl32[b * SHE + k4 * 2]     = l0;
                hl32[b * SHE + k4 * 2 + 1] = l1;
            }
            __syncthreads();

            float c[2][2][4] = {};
            #pragma unroll
            for (int ks = 0; ks < 4; ks++) {
                int kh = ksub * 32 + ks * 8;       // u32 offset into k
                unsigned ahi[2][4], alo[2][4], bhi[2][2], blo[2][2];
                #pragma unroll
                for (int mi = 0; mi < 2; mi++) {
                    ahi[mi][0] = Whi[pWr[2 * mi]     + kh + tig];
                    ahi[mi][1] = Whi[pWr[2 * mi + 1] + kh + tig];
                    ahi[mi][2] = Whi[pWr[2 * mi]     + kh + tig + 4];
                    ahi[mi][3] = Whi[pWr[2 * mi + 1] + kh + tig + 4];
                    alo[mi][0] = Wlo[pWr[2 * mi]     + kh + tig];
                    alo[mi][1] = Wlo[pWr[2 * mi + 1] + kh + tig];
                    alo[mi][2] = Wlo[pWr[2 * mi]     + kh + tig + 4];
                    alo[mi][3] = Wlo[pWr[2 * mi + 1] + kh + tig + 4];
                }
                #pragma unroll
                for (int ni = 0; ni < 2; ni++) {
                    int nr = ni * 8 + gid;
                    bhi[ni][0] = hh32[nr * SHE + kh + tig];
                    bhi[ni][1] = hh32[nr * SHE + kh + tig + 4];
                    blo[ni][0] = hl32[nr * SHE + kh + tig];
                    blo[ni][1] = hl32[nr * SHE + kh + tig + 4];
                }
                #pragma unroll
                for (int mi = 0; mi < 2; mi++)
                    #pragma unroll
                    for (int ni = 0; ni < 2; ni++) {
                        mma16816(c[mi][ni], ahi[mi], bhi[ni]);
                        mma16816(c[mi][ni], ahi[mi], blo[ni]);
                        mma16816(c[mi][ni], alo[mi], bhi[ni]);
                    }
            }
            __syncthreads();   // done reading h stage
            // partials -> red[ksub][row][batch]
            #pragma unroll
            for (int mi = 0; mi < 2; mi++) {
                int r0 = mi * 16 + gid;
                #pragma unroll
                for (int ni = 0; ni < 2; ni++) {
                    int col = ni * 8 + 2 * tig;
                    *(float2*)(red + (ksub * 32 + r0) * 16 + col) =
                        make_float2(c[mi][ni][0], c[mi][ni][1]);
                    *(float2*)(red + (ksub * 32 + r0 + 8) * 16 + col) =
                        make_float2(c[mi][ni][2], c[mi][ni][3]);
                }
            }
            __syncthreads();
            // cell: 8 j x 16 b
            if (tid < 128) {
                int b = tid >> 3, jl = tid & 7;
                int jj = j0 + jl;
                int tt = dir ? (LK - 1 - t) : t;
                float gate[4];
                #pragma unroll
                for (int g = 0; g < 4; g++) {
                    int row = g * 8 + jl;
                    float s = xg[((long)b * LK + tt) * HG + g * HH + jj];
                    #pragma unroll
                    for (int q = 0; q < 8; q++)
                        s += red[(q * 32 + row) * 16 + b];
                    gate[g] = s;
                }
                int si = dir * BB * HH + b * HH + jj;
                float cc = sigf(gate[1]) * g_ce[si] + sigf(gate[0]) * tanhf(gate[2]);
                float h = sigf(gate[3]) * tanhf(cc);
                g_ce[si] = cc;
                g_he[si] = h;
                g_enc[((long)b * LK + tt) * H2 + dir * HH + jj] = h;
            }
            gbar();
        }
    }

    // ===================== decoder init =====================
    {
        int gt = blockIdx.x * NTHR + tid;
        if (gt < BB * H2) {
            int b = gt >> 10, jj = gt & (H2 - 1);
            int dir = jj & 1, j = jj >> 1;
            g_hd[gt] = g_he[dir * BB * HH + b * HH + j];
            g_cd[gt] = g_ce[dir * BB * HH + b * HH + j];
        }
    }
    gbar();

    // ===================== decoder =====================
    {
        const int j0 = blockIdx.x * 8;
        long pWr[4];
        #pragma unroll
        for (int i = 0; i < 4; i++) {
            int r = gid + i * 8;
            int g = r >> 3, jl = r & 7;
            pWr[i] = (long)(g * H2 + j0 + jl) * (H2 / 2);
        }

        for (int t = 0; t < LQ; t++) {
            // stage h: 16 x 1024 floats -> bf16 hi/lo
            #pragma unroll
            for (int i = 0; i < 16; i++) {
                int idx = tid + i * NTHR;          // 0..4095 float4 index
                int b = idx >> 8, k4 = idx & 255;
                float4 v = ((const float4*)g_hd)[idx];
                unsigned h0, h1, l0, l1;
                bf16split4(v, h0, h1, l0, l1);
                hh32[b * SHD + k4 * 2]     = h0;
                hh32[b * SHD + k4 * 2 + 1] = h1;
                hl32[b * SHD + k4 * 2]     = l0;
                hl32[b * SHD + k4 * 2 + 1] = l1;
            }
            __syncthreads();

            float c[2][2][4] = {};
            #pragma unroll
            for (int ks = 0; ks < 8; ks++) {
                int kh = ksub * 64 + ks * 8;
                unsigned ahi[2][4], alo[2][4], bhi[2][2], blo[2][2];
                #pragma unroll
                for (int mi = 0; mi < 2; mi++) {
                    ahi[mi][0] = g_dWhi[pWr[2 * mi]     + kh + tig];
                    ahi[mi][1] = g_dWhi[pWr[2 * mi + 1] + kh + tig];
                    ahi[mi][2] = g_dWhi[pWr[2 * mi]     + kh + tig + 4];
                    ahi[mi][3] = g_dWhi[pWr[2 * mi + 1] + kh + tig + 4];
                    alo[mi][0] = g_dWlo[pWr[2 * mi]     + kh + tig];
                    alo[mi][1] = g_dWlo[pWr[2 * mi + 1] + kh + tig];
                    alo[mi][2] = g_dWlo[pWr[2 * mi]     + kh + tig + 4];
                    alo[mi][3] = g_dWlo[pWr[2 * mi + 1] + kh + tig + 4];
                }
                #pragma unroll
                for (int ni = 0; ni < 2; ni++) {
                    int nr = ni * 8 + gid;
                    bhi[ni][0] = hh32[nr * SHD + kh + tig];
                    bhi[ni][1] = hh32[nr * SHD + kh + tig + 4];
                    blo[ni][0] = hl32[nr * SHD + kh + tig];
                    blo[ni][1] = hl32[nr * SHD + kh + tig + 4];
                }
                #pragma unroll
                for (int mi = 0; mi < 2; mi++)
                    #pragma unroll
                    for (int ni = 0; ni < 2; ni++) {
                        mma16816(c[mi][ni], ahi[mi], bhi[ni]);
                        mma16816(c[mi][ni], ahi[mi], blo[ni]);
                        mma16816(c[mi][ni], alo[mi], bhi[ni]);
                    }
            }
            __syncthreads();
            #pragma unroll
            for (int mi = 0; mi < 2; mi++) {
                int r0 = mi * 16 + gid;
                #pragma unroll
                for (int ni = 0; ni < 2; ni++) {
                    int col = ni * 8 + 2 * tig;
                    *(float2*)(red + (ksub * 32 + r0) * 16 + col) =
                        make_float2(c[mi][ni][0], c[mi][ni][1]);
                    *(float2*)(red + (ksub * 32 + r0 + 8) * 16 + col) =
                        make_float2(c[mi][ni][2], c[mi][ni][3]);
                }
            }
            __syncthreads();
            if (tid < 128) {
                int b = tid >> 3, jl = tid & 7;
                int jj = j0 + jl;
                float gate[4];
                #pragma unroll
                for (int g = 0; g < 4; g++) {
                    int row = g * 8 + jl;
                    float s = g_xg_d[((long)b * LQ + t) * DG + g * H2 + jj];
                    #pragma unroll
                    for (int q = 0; q < 8; q++)
                        s += red[(q * 32 + row) * 16 + b];
                    gate[g] = s;
                }
                int ci = b * H2 + jj;
                float cc = sigf(gate[1]) * g_cd[ci] + sigf(gate[0]) * tanhf(gate[2]);
                float h = sigf(gate[3]) * tanhf(cc);
                g_cd[ci] = cc;
                g_hd[ci] = h;
                long base = (long)b * LQ + t;
                g_cat[base * (2 * H2) + H2 + jj] = h;
                g_x1[base * H2 + jj] = h;
            }
            gbar();
        }
    }
}

// ---------------- softmax over k with PAD mask ----------------
__global__ void k_softmax(const int* __restrict__ source) {
    int b = blockIdx.y, q = blockIdx.x;
    int k = threadIdx.x;
    long off = ((long)b * LQ + q) * LK;
    float s = g_att[off + k];
    if (source[b * LK + k] == 0) s = -INFINITY;
    __shared__ float red[64];
    red[k] = s;
    __syncthreads();
    #pragma unroll
    for (int st = 32; st > 0; st >>= 1) {
        if (k < st) red[k] = fmaxf(red[k], red[k + st]);
        __syncthreads();
    }
    float mx = red[0];
    __syncthreads();
    float e = expf(s - mx);
    red[k] = e;
    __syncthreads();
    #pragma unroll
    for (int st = 32; st > 0; st >>= 1) {
        if (k < st) red[k] += red[k + st];
        __syncthreads();
    }
    g_att[off + k] = e / red[0];
}

// ---------------- ctx = A @ V into first half of concat buffer ----------------
__global__ void k_ctx() {
    int b = blockIdx.z;
    int q0 = blockIdx.y * 16;
    int c = blockIdx.x * 128 + threadIdx.x;
    __shared__ float As[16][64];
    for (int i = threadIdx.x; i < 16 * 64; i += 128)
        As[i / 64][i & 63] = g_att[((long)b * LQ + q0 + i / 64) * LK + (i & 63)];
    __syncthreads();
    float acc[16] = {};
    for (int k = 0; k < LK; k++) {
        float v = g_Vb[((long)b * LK + k) * H2 + c];
        #pragma unroll
        for (int q = 0; q < 16; q++) acc[q] += As[q][k] * v;
    }
    #pragma unroll
    for (int q = 0; q < 16; q++)
        g_cat[((long)b * LQ + q0 + q) * (2 * H2) + c] = acc[q];
}

// ---------------- host launch ----------------
extern "C" void kernel_launch(void* const* d_in, const int* in_sizes, int n_in,
                              void* d_out, int out_size) {
    const int*   source   = (const int*)  d_in[0];
    const int*   prev     = (const int*)  d_in[1];
    const float* emb      = (const float*)d_in[2];
    const float* ef_Wih   = (const float*)d_in[3];
    const float* ef_Whh   = (const float*)d_in[4];
    const float* ef_b     = (const float*)d_in[5];
    const float* eb_Wih   = (const float*)d_in[6];
    const float* eb_Whh   = (const float*)d_in[7];
    const float* eb_b     = (const float*)d_in[8];
    const float* d_Wih    = (const float*)d_in[9];
    const float* d_Whh    = (const float*)d_in[10];
    const float* d_b      = (const float*)d_in[11];
    const float* k_W      = (const float*)d_in[12];
    const float* k_b      = (const float*)d_in[13];
    const float* v_W      = (const float*)d_in[14];
    const float* v_b      = (const float*)d_in[15];
    const float* fc1_W    = (const float*)d_in[16];
    const float* fc1_b    = (const float*)d_in[17];
    const float* fc2_W    = (const float*)d_in[18];
    const float* fc2_b    = (const float*)d_in[19];
    float* out = (float*)d_out;

    float *p_xs_src, *p_xs_prev, *p_xg_f, *p_xg_b, *p_xg_d;
    float *p_enc, *p_K, *p_V, *p_att, *p_cat, *p_x1;
    unsigned *p_eWhi, *p_eWlo, *p_dWhi, *p_dWlo;
    cudaGetSymbolAddress((void**)&p_xs_src, g_xs_src);
    cudaGetSymbolAddress((void**)&p_xs_prev, g_xs_prev);
    cudaGetSymbolAddress((void**)&p_xg_f, g_xg_f);
    cudaGetSymbolAddress((void**)&p_xg_b, g_xg_b);
    cudaGetSymbolAddress((void**)&p_xg_d, g_xg_d);
    cudaGetSymbolAddress((void**)&p_enc, g_enc);
    cudaGetSymbolAddress((void**)&p_K, g_Kb);
    cudaGetSymbolAddress((void**)&p_V, g_Vb);
    cudaGetSymbolAddress((void**)&p_att, g_att);
    cudaGetSymbolAddress((void**)&p_cat, g_cat);
    cudaGetSymbolAddress((void**)&p_x1, g_x1);
    cudaGetSymbolAddress((void**)&p_eWhi, g_eWhi);
    cudaGetSymbolAddress((void**)&p_eWlo, g_eWlo);
    cudaGetSymbolAddress((void**)&p_dWhi, g_dWhi);
    cudaGetSymbolAddress((void**)&p_dWlo, g_dWlo);

    const int dyn_smem = (2 * 16 * SHD + 8 * 32 * 16) * 4;   // 82432 B
    cudaFuncSetAttribute(k_recurrence, cudaFuncAttributeMaxDynamicSharedMemorySize, dyn_smem);

    // 0-1. embeddings
    k_embed<<<(BB * LK * DD + 255) / 256, 256>>>(source, emb, p_xs_src, BB * LK);
    k_embed<<<(BB * LQ * DD + 255) / 256, 256>>>(prev, emb, p_xs_prev, BB * LQ);

    // 2-4. bf16 hi/lo weight split for recurrence
    {
        int n2e = HG * HH / 2;
        int n2d = DG * H2 / 2;
        k_wsplit<<<(n2e + 255) / 256, 256>>>(ef_Whh, p_eWhi, p_eWlo, n2e);
        k_wsplit<<<(n2e + 255) / 256, 256>>>(eb_Whh, p_eWhi + n2e, p_eWlo + n2e, n2e);
        k_wsplit<<<(n2d + 255) / 256, 256>>>(d_Whh, p_dWhi, p_dWlo, n2d);
    }

    // 5-7. input pregates (tf32 mma)
    k_tgemm<<<dim3(HG / 128, (BB * LK) / 128), 256>>>(p_xs_src, ef_Wih, ef_b, p_xg_f,
        BB * LK, HG, DD, 0);
    k_tgemm<<<dim3(HG / 128, (BB * LK) / 128), 256>>>(p_xs_src, eb_Wih, eb_b, p_xg_b,
        BB * LK, HG, DD, 0);
    k_tgemm<<<dim3(DG / 128, (BB * LQ) / 128), 256>>>(p_xs_prev, d_Wih, d_b, p_xg_d,
        BB * LQ, DG, DD, 0);

    // 8. full recurrence (tensor-core bf16-split matvec)
    k_recurrence<<<NBLK, NTHR, dyn_smem>>>();

    // 9-10. K and V projections
    k_tgemm<<<dim3(H2 / 128, (BB * LK) / 128), 256>>>(p_enc, k_W, k_b, p_K,
        BB * LK, H2, H2, 0);
    k_tgemm<<<dim3(H2 / 128, (BB * LK) / 128), 256>>>(p_enc, v_W, v_b, p_V,
        BB * LK, H2, H2, 0);

    // 11. scores (fp32, Q stored in g_x1)
    k_gemm<<<dim3(1, 1, BB), dim3(16, 16)>>>(p_x1, p_K, nullptr, p_att,
        LQ, LK, H2, (long)LQ * H2, (long)LK * H2, (long)LQ * LK, 0);

    // 12. masked softmax
    k_softmax<<<dim3(LQ, BB), 64>>>(source);

    // 13. ctx = A @ V
    k_ctx<<<dim3(H2 / 128, LQ / 16, BB), 128>>>();

    // 14. fc1 with tanh (overwrites Q temp storage)
    k_tgemm<<<dim3(H2 / 128, (BB * LQ) / 128), 256>>>(p_cat, fc1_W, fc1_b, p_x1,
        BB * LQ, H2, 2 * H2, 1);

    // 15. fc2
    k_tgemm<<<dim3((VV + 127) / 128, (BB * LQ) / 128), 256>>>(p_x1, fc2_W, fc2_b, out,
        BB * LQ, VV, H2, 0);
}

// round 17
// speedup vs baseline: 1.8888x; 1.2678x over previous
#include <cuda_runtime.h>
#include <math.h>
#include <stdint.h>

// ---------------- problem constants ----------------
#define BB   16      // batch
#define LK   64      // source length
#define LQ   64      // query length
#define DD   300     // embedding dim
#define HH   512     // encoder hidden
#define H2   1024    // 2*H (decoder hidden / enc_out channels)
#define HG   2048    // 4*H  encoder gates
#define DG   4096    // 8*H  decoder gates
#define VV   10000   // vocab

#define NBLK 128
#define NTHR 256

// smem strides (u32 units), stride % 32 == 4 -> conflict-free frags
#define SHD  516     // dec h row stride: 1024/2 + 4
#define SHE  260     // enc h row stride: 512/2 + 4

// fragment-ordered weight array sizes (uint4 units)
#define EW4  131072  // per dir: 64 blk x 8 ksub x 4 ks x 2 mi x 32 lane
#define DW4  524288  // 128 blk x 8 ksub x 8 ks x 2 mi x 32 lane

// ---------------- scratch (device globals; no allocation) ----------------
__device__ float g_xs_src[BB * LK * DD];
__device__ float g_xs_prev[BB * LQ * DD];
__device__ float g_xg_f[BB * LK * HG];
__device__ float g_xg_b[BB * LK * HG];
__device__ float g_xg_d[BB * LQ * DG];
__device__ float g_ce[2 * BB * HH];
__device__ float g_he[2 * BB * HH];   // enc h: (dir, b, j)
__device__ float g_cd[BB * H2];
__device__ float g_hd[BB * H2];       // dec h: (b, jj)
__device__ float g_enc[BB * LK * H2];
__device__ float g_Kb[BB * LK * H2];
__device__ float g_Vb[BB * LK * H2];
__device__ float g_att[BB * LQ * LK];
__device__ float g_cat[BB * LQ * 2 * H2];
__device__ float g_x1[BB * LQ * H2];

// fragment-ordered bf16 hi/lo recurrent weights
__device__ uint4 g_eWhi[2 * EW4];
__device__ uint4 g_eWlo[2 * EW4];
__device__ uint4 g_dWhi[DW4];
__device__ uint4 g_dWlo[DW4];

// grid barrier state: slots 0,1 = encoder dirs (64 blocks); slot 2 = full (128)
__device__ unsigned g_bcnt[3] = {0, 0, 0};
__device__ unsigned g_bgen[3] = {0, 0, 0};

__device__ __forceinline__ float sigf(float x) { return 1.f / (1.f + expf(-x)); }

__device__ __forceinline__ void gbarn(int slot, unsigned count) {
    __syncthreads();
    if (threadIdx.x == 0) {
        volatile unsigned* genp = &g_bgen[slot];
        __threadfence();
        unsigned g = *genp;
        if (atomicAdd(&g_bcnt[slot], 1u) == count - 1) {
            g_bcnt[slot] = 0;
            __threadfence();
            *genp = g + 1;
        } else {
            while (*genp == g) { }
            __threadfence();
        }
    }
    __syncthreads();
}

// ---------------- mma helpers ----------------
__device__ __forceinline__ unsigned f2tf32(float f) {
    unsigned r;
    asm("cvt.rna.tf32.f32 %0, %1;" : "=r"(r) : "f"(f));
    return r;
}

__device__ __forceinline__ void mma1688(float c[4], const unsigned a[4], const unsigned b[2]) {
    asm volatile(
        "mma.sync.aligned.m16n8k8.row.col.f32.tf32.tf32.f32 "
        "{%0,%1,%2,%3}, {%4,%5,%6,%7}, {%8,%9}, {%0,%1,%2,%3};"
        : "+f"(c[0]), "+f"(c[1]), "+f"(c[2]), "+f"(c[3])
        : "r"(a[0]), "r"(a[1]), "r"(a[2]), "r"(a[3]), "r"(b[0]), "r"(b[1]));
}

__device__ __forceinline__ void mma16816(float c[4], const unsigned a[4], const unsigned b[2]) {
    asm volatile(
        "mma.sync.aligned.m16n8k16.row.col.f32.bf16.bf16.f32 "
        "{%0,%1,%2,%3}, {%4,%5,%6,%7}, {%8,%9}, {%0,%1,%2,%3};"
        : "+f"(c[0]), "+f"(c[1]), "+f"(c[2]), "+f"(c[3])
        : "r"(a[0]), "r"(a[1]), "r"(a[2]), "r"(a[3]), "r"(b[0]), "r"(b[1]));
}

__device__ __forceinline__ unsigned packbf(float x, float y) {
    unsigned r;
    asm("cvt.rn.bf16x2.f32 %0, %1, %2;" : "=r"(r) : "f"(y), "f"(x));
    return r;
}

__device__ __forceinline__ void bf16split4(float4 v, unsigned& hi0, unsigned& hi1,
                                           unsigned& lo0, unsigned& lo1) {
    hi0 = packbf(v.x, v.y);
    hi1 = packbf(v.z, v.w);
    float h0 = __uint_as_float(hi0 << 16), h1 = __uint_as_float(hi0 & 0xffff0000u);
    float h2 = __uint_as_float(hi1 << 16), h3 = __uint_as_float(hi1 & 0xffff0000u);
    lo0 = packbf(v.x - h0, v.y - h1);
    lo1 = packbf(v.z - h2, v.w - h3);
}

// ---------------- small utility kernels ----------------
__global__ void k_embed(const int* __restrict__ idx, const float* __restrict__ emb,
                        float* __restrict__ out, int rows) {
    int i = blockIdx.x * blockDim.x + threadIdx.x;
    if (i < rows * DD) {
        int r = i / DD, d = i - r * DD;
        out[i] = emb[(long)idx[r] * DD + d];
    }
}

// ---- weight prep: split fp32 -> bf16 hi/lo AND swizzle into mma-fragment order ----
// Output uint4 t encodes (bx, ksub, ks, mi, lane); the 4 u32 are the A-fragment
// registers a[0..3] = W[row(gid + (2mi+{0,1})*8)][kh + tig (+4)] bf16 pairs.
__global__ void k_wprep(const float* __restrict__ src, uint4* __restrict__ hi4,
                        uint4* __restrict__ lo4, int nks, int K, int H, int nout) {
    int t = blockIdx.x * blockDim.x + threadIdx.x;
    if (t >= nout) return;
    int u = t;
    int lane = u & 31; u >>= 5;
    int mi = u & 1; u >>= 1;
    int ks = u % nks; u /= nks;
    int ksub = u & 7; u >>= 3;
    int bx = u;
    int gid = lane >> 2, tig = lane & 3;
    int kh = ksub * (K / 16) + ks * 8;    // u32 (bf16-pair) offset within row
    unsigned h[4], l[4];
    #pragma unroll
    for (int c = 0; c < 4; c++) {
        int i = 2 * mi + (c & 1);
        int koff = kh + tig + ((c >= 2) ? 4 : 0);
        int r = gid + i * 8;
        int g = r >> 3, jl = r & 7;
        long row = (long)g * H + bx * 8 + jl;
        float2 v = *(const float2*)(src + row * K + koff * 2);
        unsigned hh = packbf(v.x, v.y);
        float h0 = __uint_as_float(hh << 16), h1 = __uint_as_float(hh & 0xffff0000u);
        h[c] = hh;
        l[c] = packbf(v.x - h0, v.y - h1);
    }
    hi4[t] = make_uint4(h[0], h[1], h[2], h[3]);
    lo4[t] = make_uint4(l[0], l[1], l[2], l[3]);
}

// ---------------- tf32 tensor-core GEMM (proven R13 config) --------
#define ASTRIDE 36
__global__ void __launch_bounds__(256, 1)
k_tgemm(const float* __restrict__ A, const float* __restrict__ W,
        const float* __restrict__ bias, float* __restrict__ C,
        int M, int N, int K, int act) {
    __shared__ unsigned As[128 * ASTRIDE];
    __shared__ unsigned Ws[128 * ASTRIDE];
    const int tid = threadIdx.x;
    const int warp = tid >> 5, lane = tid & 31;
    const int wm = warp >> 2, wn = warp & 3;
    const int gid = lane >> 2, tig = lane & 3;
    const int m0 = blockIdx.y * 128, n0 = blockIdx.x * 128;
    float acc[4][4][4] = {};
    const int nch = (K + 31) / 32;
    float4 pa[4], pw[4];

    {
        #pragma unroll
        for (int s = 0; s < 4; s++) {
            int idx = tid + s * 256;
            int row = idx >> 3, c4 = (idx & 7) * 4;
            int kb = c4;
            float4 va = make_float4(0.f, 0.f, 0.f, 0.f);
            if (m0 + row < M) {
                if (kb + 3 < K) va = *(const float4*)(A + (long)(m0 + row) * K + kb);
                else {
                    const float* p = A + (long)(m0 + row) * K;
                    va.x = (kb + 0 < K) ? p[kb + 0] : 0.f;
                    va.y = (kb + 1 < K) ? p[kb + 1] : 0.f;
                    va.z = (kb + 2 < K) ? p[kb + 2] : 0.f;
                    va.w = (kb + 3 < K) ? p[kb + 3] : 0.f;
                }
            }
            pa[s] = va;
            float4 vw = make_float4(0.f, 0.f, 0.f, 0.f);
            if (n0 + row < N) {
                if (kb + 3 < K) vw = *(const float4*)(W + (long)(n0 + row) * K + kb);
                else {
                    const float* p = W + (long)(n0 + row) * K;
                    vw.x = (kb + 0 < K) ? p[kb + 0] : 0.f;
                    vw.y = (kb + 1 < K) ? p[kb + 1] : 0.f;
                    vw.z = (kb + 2 < K) ? p[kb + 2] : 0.f;
                    vw.w = (kb + 3 < K) ? p[kb + 3] : 0.f;
                }
            }
            pw[s] = vw;
        }
    }

    for (int ch = 0; ch < nch; ch++) {
        __syncthreads();
        #pragma unroll
        for (int s = 0; s < 4; s++) {
            int idx = tid + s * 256;
            int row = idx >> 3, c4 = (idx & 7) * 4;
            uint4 ua;
            ua.x = f2tf32(pa[s].x); ua.y = f2tf32(pa[s].y);
            ua.z = f2tf32(pa[s].z); ua.w = f2tf32(pa[s].w);
            *(uint4*)(As + row * ASTRIDE + c4) = ua;
            uint4 uw;
            uw.x = f2tf32(pw[s].x); uw.y = f2tf32(pw[s].y);
            uw.z = f2tf32(pw[s].z); uw.w = f2tf32(pw[s].w);
            *(uint4*)(Ws + row * ASTRIDE + c4) = uw;
        }
        __syncthreads();

        if (ch + 1 < nch) {
            const int kk = (ch + 1) * 32;
            #pragma unroll
            for (int s = 0; s < 4; s++) {
                int idx = tid + s * 256;
                int row = idx >> 3, c4 = (idx & 7) * 4;
                int kb = kk + c4;
                float4 va = make_float4(0.f, 0.f, 0.f, 0.f);
                if (m0 + row < M) {
                    if (kb + 3 < K) va = *(const float4*)(A + (long)(m0 + row) * K + kb);
                    else {
                        const float* p = A + (long)(m0 + row) * K;
                        va.x = (kb + 0 < K) ? p[kb + 0] : 0.f;
                        va.y = (kb + 1 < K) ? p[kb + 1] : 0.f;
                        va.z = (kb + 2 < K) ? p[kb + 2] : 0.f;
                        va.w = (kb + 3 < K) ? p[kb + 3] : 0.f;
                    }
                }
                pa[s] = va;
                float4 vw = make_float4(0.f, 0.f, 0.f, 0.f);
                if (n0 + row < N) {
                    if (kb + 3 < K) vw = *(const float4*)(W + (long)(n0 + row) * K + kb);
                    else {
                        const float* p = W + (long)(n0 + row) * K;
                        vw.x = (kb + 0 < K) ? p[kb + 0] : 0.f;
                        vw.y = (kb + 1 < K) ? p[kb + 1] : 0.f;
                        vw.z = (kb + 2 < K) ? p[kb + 2] : 0.f;
                        vw.w = (kb + 3 < K) ? p[kb + 3] : 0.f;
                    }
                }
                pw[s] = vw;
            }
        }

        #pragma unroll
        for (int ki = 0; ki < 4; ki++) {
            const int k0 = ki * 8;
            unsigned a[4][4], b[4][2];
            #pragma unroll
            for (int mi = 0; mi < 4; mi++) {
                int mr = wm * 64 + mi * 16;
                a[mi][0] = As[(mr + gid)     * ASTRIDE + k0 + tig];
                a[mi][1] = As[(mr + gid + 8) * ASTRIDE + k0 + tig];
                a[mi][2] = As[(mr + gid)     * ASTRIDE + k0 + tig + 4];
                a[mi][3] = As[(mr + gid + 8) * ASTRIDE + k0 + tig + 4];
            }
            #pragma unroll
            for (int ni = 0; ni < 4; ni++) {
                int nr = wn * 32 + ni * 8;
                b[ni][0] = Ws[(nr + gid) * ASTRIDE + k0 + tig];
                b[ni][1] = Ws[(nr + gid) * ASTRIDE + k0 + tig + 4];
            }
            #pragma unroll
            for (int mi = 0; mi < 4; mi++)
                #pragma unroll
                for (int ni = 0; ni < 4; ni++)
                    mma1688(acc[mi][ni], a[mi], b[ni]);
        }
    }

    #pragma unroll
    for (int mi = 0; mi < 4; mi++) {
        int m1 = m0 + wm * 64 + mi * 16 + gid;
        int m2 = m1 + 8;
        #pragma unroll
        for (int ni = 0; ni < 4; ni++) {
            int nc = n0 + wn * 32 + ni * 8 + 2 * tig;
            float b0 = 0.f, b1 = 0.f;
            if (bias) {
                if (nc < N)     b0 = bias[nc];
                if (nc + 1 < N) b1 = bias[nc + 1];
            }
            float v0 = acc[mi][ni][0] + b0;
            float v1 = acc[mi][ni][1] + b1;
            float v2 = acc[mi][ni][2] + b0;
            float v3 = acc[mi][ni][3] + b1;
            if (act == 1) { v0 = tanhf(v0); v1 = tanhf(v1); v2 = tanhf(v2); v3 = tanhf(v3); }
            if (m1 < M) {
                if (nc < N)     C[(long)m1 * N + nc]     = v0;
                if (nc + 1 < N) C[(long)m1 * N + nc + 1] = v1;
            }
            if (m2 < M) {
                if (nc < N)     C[(long)m2 * N + nc]     = v2;
                if (nc + 1 < N) C[(long)m2 * N + nc + 1] = v3;
            }
        }
    }
}

// ---------------- small batched GEMM for attention scores (fp32) ----------------
__global__ void k_gemm(const float* __restrict__ A, const float* __restrict__ W,
                       const float* __restrict__ bias, float* __restrict__ C,
                       int M, int N, int K, long sA, long sW, long sC, int act) {
    A += (long)blockIdx.z * sA;
    W += (long)blockIdx.z * sW;
    C += (long)blockIdx.z * sC;
    __shared__ float As[16][68];
    __shared__ float Ws[16][68];
    int m0 = blockIdx.y * 64, n0 = blockIdx.x * 64;
    int tx = threadIdx.x, ty = threadIdx.y;
    int tid = ty * 16 + tx;
    float acc[4][4] = {};
    for (int kk = 0; kk < K; kk += 16) {
        #pragma unroll
        for (int s = 0; s < 4; s++) {
            int e = tid + s * 256;
            int mm = e >> 4, k = e & 15;
            float va = 0.f, vw = 0.f;
            if (m0 + mm < M && kk + k < K) va = A[(long)(m0 + mm) * K + kk + k];
            if (n0 + mm < N && kk + k < K) vw = W[(long)(n0 + mm) * K + kk + k];
            As[k][mm] = va;
            Ws[k][mm] = vw;
        }
        __syncthreads();
        #pragma unroll
        for (int k = 0; k < 16; k++) {
            float a[4], w[4];
            #pragma unroll
            for (int i = 0; i < 4; i++) a[i] = As[k][ty * 4 + i];
            #pragma unroll
            for (int j = 0; j < 4; j++) w[j] = Ws[k][tx * 4 + j];
            #pragma unroll
            for (int i = 0; i < 4; i++)
                #pragma unroll
                for (int j = 0; j < 4; j++) acc[i][j] += a[i] * w[j];
        }
        __syncthreads();
    }
    #pragma unroll
    for (int i = 0; i < 4; i++) {
        int m = m0 + ty * 4 + i;
        if (m >= M) continue;
        #pragma unroll
        for (int j = 0; j < 4; j++) {
            int n = n0 + tx * 4 + j;
            if (n >= N) continue;
            float v = acc[i][j];
            if (bias) v += bias[n];
            if (act == 1) v = tanhf(v);
            C[(long)m * N + n] = v;
        }
    }
}

// ---------------- persistent recurrence: bf16-split mma, fragment-ordered W --------
__global__ void __launch_bounds__(NTHR, 1)
k_recurrence() {
    extern __shared__ unsigned dsh[];
    unsigned* hh32 = dsh;
    unsigned* hl32 = dsh + 16 * SHD;
    float* red = (float*)(dsh + 2 * 16 * SHD);   // [8][32][16]

    const int tid = threadIdx.x;
    const int lane = tid & 31;
    const int ksub = tid >> 5;
    const int gid = lane >> 2, tig = lane & 3;

    // ---- zero encoder state ----
    {
        int gt = blockIdx.x * NTHR + tid;
        if (gt < 2 * BB * HH) { g_ce[gt] = 0.f; g_he[gt] = 0.f; }
    }
    gbarn(2, NBLK);

    // ===================== encoder (per-dir barrier groups of 64) =====================
    {
        const int dir = blockIdx.x >> 6;
        const int bx = blockIdx.x & 63;
        const int j0 = bx * 8;
        const float* xg = dir ? g_xg_b : g_xg_f;
        const float* hsrc = g_he + dir * BB * HH;
        const long wb = (long)dir * EW4 + ((long)(bx * 8 + ksub) * 4) * 64 + lane;

        for (int t = 0; t < LK; t++) {
            // stage h: 16 x 512 floats -> bf16 hi/lo
            #pragma unroll
            for (int i = 0; i < 8; i++) {
                int idx = tid + i * NTHR;
                int b = idx >> 7, k4 = idx & 127;
                float4 v = ((const float4*)hsrc)[idx];
                unsigned h0, h1, l0, l1;
                bf16split4(v, h0, h1, l0, l1);
                hh32[b * SHE + k4 * 2]     = h0;
                hh32[b * SHE + k4 * 2 + 1] = h1;
                hl32[b * SHE + k4 * 2]     = l0;
                hl32[b * SHE + k4 * 2 + 1] = l1;
            }
            __syncthreads();

            float c[2][2][4] = {};
            #pragma unroll
            for (int ks = 0; ks < 4; ks++) {
                int kh = ksub * 32 + ks * 8;
                uint4 ah[2], al[2];
                ah[0] = g_eWhi[wb + ks * 64];
                ah[1] = g_eWhi[wb + ks * 64 + 32];
                al[0] = g_eWlo[wb + ks * 64];
                al[1] = g_eWlo[wb + ks * 64 + 32];
                unsigned bhi[2][2], blo[2][2];
                #pragma unroll
                for (int ni = 0; ni < 2; ni++) {
                    int nr = ni * 8 + gid;
                    bhi[ni][0] = hh32[nr * SHE + kh + tig];
                    bhi[ni][1] = hh32[nr * SHE + kh + tig + 4];
                    blo[ni][0] = hl32[nr * SHE + kh + tig];
                    blo[ni][1] = hl32[nr * SHE + kh + tig + 4];
                }
                #pragma unroll
                for (int mi = 0; mi < 2; mi++)
                    #pragma unroll
                    for (int ni = 0; ni < 2; ni++) {
                        mma16816(c[mi][ni], (const unsigned*)&ah[mi], bhi[ni]);
                        mma16816(c[mi][ni], (const unsigned*)&ah[mi], blo[ni]);
                        mma16816(c[mi][ni], (const unsigned*)&al[mi], bhi[ni]);
                    }
            }
            __syncthreads();
            #pragma unroll
            for (int mi = 0; mi < 2; mi++) {
                int r0 = mi * 16 + gid;
                #pragma unroll
                for (int ni = 0; ni < 2; ni++) {
                    int col = ni * 8 + 2 * tig;
                    *(float2*)(red + (ksub * 32 + r0) * 16 + col) =
                        make_float2(c[mi][ni][0], c[mi][ni][1]);
                    *(float2*)(red + (ksub * 32 + r0 + 8) * 16 + col) =
                        make_float2(c[mi][ni][2], c[mi][ni][3]);
                }
            }
            __syncthreads();
            if (tid < 128) {
                int b = tid >> 3, jl = tid & 7;
                int jj = j0 + jl;
                int tt = dir ? (LK - 1 - t) : t;
                float gate[4];
                #pragma unroll
                for (int g = 0; g < 4; g++) {
                    int row = g * 8 + jl;
                    float s = xg[((long)b * LK + tt) * HG + g * HH + jj];
                    #pragma unroll
                    for (int q = 0; q < 8; q++)
                        s += red[(q * 32 + row) * 16 + b];
                    gate[g] = s;
                }
                int si = dir * BB * HH + b * HH + jj;
                float cc = sigf(gate[1]) * g_ce[si] + sigf(gate[0]) * tanhf(gate[2]);
                float h = sigf(gate[3]) * tanhf(cc);
                g_ce[si] = cc;
                g_he[si] = h;
                g_enc[((long)b * LK + tt) * H2 + dir * HH + jj] = h;
            }
            gbarn(dir, 64);
        }
    }
    gbarn(2, NBLK);

    // ===================== decoder init =====================
    {
        int gt = blockIdx.x * NTHR + tid;
        if (gt < BB * H2) {
            int b = gt >> 10, jj = gt & (H2 - 1);
            int dir = jj & 1, j = jj >> 1;
            g_hd[gt] = g_he[dir * BB * HH + b * HH + j];
            g_cd[gt] = g_ce[dir * BB * HH + b * HH + j];
        }
    }
    gbarn(2, NBLK);

    // ===================== decoder =====================
    {
        const int j0 = blockIdx.x * 8;
        const long wb = ((long)(blockIdx.x * 8 + ksub) * 8) * 64 + lane;

        for (int t = 0; t < LQ; t++) {
            // stage h: 16 x 1024 floats -> bf16 hi/lo
            #pragma unroll
            for (int i = 0; i < 16; i++) {
                int idx = tid + i * NTHR;
                int b = idx >> 8, k4 = idx & 255;
                float4 v = ((const float4*)g_hd)[idx];
                unsigned h0, h1, l0, l1;
                bf16split4(v, h0, h1, l0, l1);
                hh32[b * SHD + k4 * 2]     = h0;
                hh32[b * SHD + k4 * 2 + 1] = h1;
                hl32[b * SHD + k4 * 2]     = l0;
                hl32[b * SHD + k4 * 2 + 1] = l1;
            }
            __syncthreads();

            float c[2][2][4] = {};
            #pragma unroll
            for (int ks = 0; ks < 8; ks++) {
                int kh = ksub * 64 + ks * 8;
                uint4 ah[2], al[2];
                ah[0] = g_dWhi[wb + ks * 64];
                ah[1] = g_dWhi[wb + ks * 64 + 32];
                al[0] = g_dWlo[wb + ks * 64];
                al[1] = g_dWlo[wb + ks * 64 + 32];
                unsigned bhi[2][2], blo[2][2];
                #pragma unroll
                for (int ni = 0; ni < 2; ni++) {
                    int nr = ni * 8 + gid;
                    bhi[ni][0] = hh32[nr * SHD + kh + tig];
                    bhi[ni][1] = hh32[nr * SHD + kh + tig + 4];
                    blo[ni][0] = hl32[nr * SHD + kh + tig];
                    blo[ni][1] = hl32[nr * SHD + kh + tig + 4];
                }
                #pragma unroll
                for (int mi = 0; mi < 2; mi++)
                    #pragma unroll
                    for (int ni = 0; ni < 2; ni++) {
                        mma16816(c[mi][ni], (const unsigned*)&ah[mi], bhi[ni]);
                        mma16816(c[mi][ni], (const unsigned*)&ah[mi], blo[ni]);
                        mma16816(c[mi][ni], (const unsigned*)&al[mi], bhi[ni]);
                    }
            }
            __syncthreads();
            #pragma unroll
            for (int mi = 0; mi < 2; mi++) {
                int r0 = mi * 16 + gid;
                #pragma unroll
                for (int ni = 0; ni < 2; ni++) {
                    int col = ni * 8 + 2 * tig;
                    *(float2*)(red + (ksub * 32 + r0) * 16 + col) =
                        make_float2(c[mi][ni][0], c[mi][ni][1]);
                    *(float2*)(red + (ksub * 32 + r0 + 8) * 16 + col) =
                        make_float2(c[mi][ni][2], c[mi][ni][3]);
                }
            }
            __syncthreads();
            if (tid < 128) {
                int b = tid >> 3, jl = tid & 7;
                int jj = j0 + jl;
                float gate[4];
                #pragma unroll
                for (int g = 0; g < 4; g++) {
                    int row = g * 8 + jl;
                    float s = g_xg_d[((long)b * LQ + t) * DG + g * H2 + jj];
                    #pragma unroll
                    for (int q = 0; q < 8; q++)
                        s += red[(q * 32 + row) * 16 + b];
                    gate[g] = s;
                }
                int ci = b * H2 + jj;
                float cc = sigf(gate[1]) * g_cd[ci] + sigf(gate[0]) * tanhf(gate[2]);
                float h = sigf(gate[3]) * tanhf(cc);
                g_cd[ci] = cc;
                g_hd[ci] = h;
                long base = (long)b * LQ + t;
                g_cat[base * (2 * H2) + H2 + jj] = h;
                g_x1[base * H2 + jj] = h;
            }
            gbarn(2, NBLK);
        }
    }
}

// ---------------- softmax over k with PAD mask ----------------
__global__ void k_softmax(const int* __restrict__ source) {
    int b = blockIdx.y, q = blockIdx.x;
    int k = threadIdx.x;
    long off = ((long)b * LQ + q) * LK;
    float s = g_att[off + k];
    if (source[b * LK + k] == 0) s = -INFINITY;
    __shared__ float red[64];
    red[k] = s;
    __syncthreads();
    #pragma unroll
    for (int st = 32; st > 0; st >>= 1) {
        if (k < st) red[k] = fmaxf(red[k], red[k + st]);
        __syncthreads();
    }
    float mx = red[0];
    __syncthreads();
    float e = expf(s - mx);
    red[k] = e;
    __syncthreads();
    #pragma unroll
    for (int st = 32; st > 0; st >>= 1) {
        if (k < st) red[k] += red[k + st];
        __syncthreads();
    }
    g_att[off + k] = e / red[0];
}

// ---------------- ctx = A @ V into first half of concat buffer ----------------
__global__ void k_ctx() {
    int b = blockIdx.z;
    int q0 = blockIdx.y * 16;
    int c = blockIdx.x * 128 + threadIdx.x;
    __shared__ float As[16][64];
    for (int i = threadIdx.x; i < 16 * 64; i += 128)
        As[i / 64][i & 63] = g_att[((long)b * LQ + q0 + i / 64) * LK + (i & 63)];
    __syncthreads();
    float acc[16] = {};
    for (int k = 0; k < LK; k++) {
        float v = g_Vb[((long)b * LK + k) * H2 + c];
        #pragma unroll
        for (int q = 0; q < 16; q++) acc[q] += As[q][k] * v;
    }
    #pragma unroll
    for (int q = 0; q < 16; q++)
        g_cat[((long)b * LQ + q0 + q) * (2 * H2) + c] = acc[q];
}

// ---------------- host launch ----------------
extern "C" void kernel_launch(void* const* d_in, const int* in_sizes, int n_in,
                              void* d_out, int out_size) {
    const int*   source   = (const int*)  d_in[0];
    const int*   prev     = (const int*)  d_in[1];
    const float* emb      = (const float*)d_in[2];
    const float* ef_Wih   = (const float*)d_in[3];
    const float* ef_Whh   = (const float*)d_in[4];
    const float* ef_b     = (const float*)d_in[5];
    const float* eb_Wih   = (const float*)d_in[6];
    const float* eb_Whh   = (const float*)d_in[7];
    const float* eb_b     = (const float*)d_in[8];
    const float* d_Wih    = (const float*)d_in[9];
    const float* d_Whh    = (const float*)d_in[10];
    const float* d_b      = (const float*)d_in[11];
    const float* k_W      = (const float*)d_in[12];
    const float* k_b      = (const float*)d_in[13];
    const float* v_W      = (const float*)d_in[14];
    const float* v_b      = (const float*)d_in[15];
    const float* fc1_W    = (const float*)d_in[16];
    const float* fc1_b    = (const float*)d_in[17];
    const float* fc2_W    = (const float*)d_in[18];
    const float* fc2_b    = (const float*)d_in[19];
    float* out = (float*)d_out;

    float *p_xs_src, *p_xs_prev, *p_xg_f, *p_xg_b, *p_xg_d;
    float *p_enc, *p_K, *p_V, *p_att, *p_cat, *p_x1;
    uint4 *p_eWhi, *p_eWlo, *p_dWhi, *p_dWlo;
    cudaGetSymbolAddress((void**)&p_xs_src, g_xs_src);
    cudaGetSymbolAddress((void**)&p_xs_prev, g_xs_prev);
    cudaGetSymbolAddress((void**)&p_xg_f, g_xg_f);
    cudaGetSymbolAddress((void**)&p_xg_b, g_xg_b);
    cudaGetSymbolAddress((void**)&p_xg_d, g_xg_d);
    cudaGetSymbolAddress((void**)&p_enc, g_enc);
    cudaGetSymbolAddress((void**)&p_K, g_Kb);
    cudaGetSymbolAddress((void**)&p_V, g_Vb);
    cudaGetSymbolAddress((void**)&p_att, g_att);
    cudaGetSymbolAddress((void**)&p_cat, g_cat);
    cudaGetSymbolAddress((void**)&p_x1, g_x1);
    cudaGetSymbolAddress((void**)&p_eWhi, g_eWhi);
    cudaGetSymbolAddress((void**)&p_eWlo, g_eWlo);
    cudaGetSymbolAddress((void**)&p_dWhi, g_dWhi);
    cudaGetSymbolAddress((void**)&p_dWlo, g_dWlo);

    const int dyn_smem = (2 * 16 * SHD + 8 * 32 * 16) * 4;   // 82432 B
    cudaFuncSetAttribute(k_recurrence, cudaFuncAttributeMaxDynamicSharedMemorySize, dyn_smem);

    // 0-1. embeddings
    k_embed<<<(BB * LK * DD + 255) / 256, 256>>>(source, emb, p_xs_src, BB * LK);
    k_embed<<<(BB * LQ * DD + 255) / 256, 256>>>(prev, emb, p_xs_prev, BB * LQ);

    // 2-4. fragment-ordered bf16 hi/lo weight prep
    k_wprep<<<(EW4 + 255) / 256, 256>>>(ef_Whh, p_eWhi, p_eWlo, 4, HH, HH, EW4);
    k_wprep<<<(EW4 + 255) / 256, 256>>>(eb_Whh, p_eWhi + EW4, p_eWlo + EW4, 4, HH, HH, EW4);
    k_wprep<<<(DW4 + 255) / 256, 256>>>(d_Whh, p_dWhi, p_dWlo, 8, H2, H2, DW4);

    // 5-7. input pregates (tf32 mma)
    k_tgemm<<<dim3(HG / 128, (BB * LK) / 128), 256>>>(p_xs_src, ef_Wih, ef_b, p_xg_f,
        BB * LK, HG, DD, 0);
    k_tgemm<<<dim3(HG / 128, (BB * LK) / 128), 256>>>(p_xs_src, eb_Wih, eb_b, p_xg_b,
        BB * LK, HG, DD, 0);
    k_tgemm<<<dim3(DG / 128, (BB * LQ) / 128), 256>>>(p_xs_prev, d_Wih, d_b, p_xg_d,
        BB * LQ, DG, DD, 0);

    // 8. full recurrence
    k_recurrence<<<NBLK, NTHR, dyn_smem>>>();

    // 9-10. K and V projections
    k_tgemm<<<dim3(H2 / 128, (BB * LK) / 128), 256>>>(p_enc, k_W, k_b, p_K,
        BB * LK, H2, H2, 0);
    k_tgemm<<<dim3(H2 / 128, (BB * LK) / 128), 256>>>(p_enc, v_W, v_b, p_V,
        BB * LK, H2, H2, 0);

    // 11. scores (fp32, Q stored in g_x1)
    k_gemm<<<dim3(1, 1, BB), dim3(16, 16)>>>(p_x1, p_K, nullptr, p_att,
        LQ, LK, H2, (long)LQ * H2, (long)LK * H2, (long)LQ * LK, 0);

    // 12. masked softmax
    k_softmax<<<dim3(LQ, BB), 64>>>(source);

    // 13. ctx = A @ V
    k_ctx<<<dim3(H2 / 128, LQ / 16, BB), 128>>>();

    // 14. fc1 with tanh (overwrites Q temp storage)
    k_tgemm<<<dim3(H2 / 128, (BB * LQ) / 128), 256>>>(p_cat, fc1_W, fc1_b, p_x1,
        BB * LQ, H2, 2 * H2, 1);

    // 15. fc2
    k_tgemm<<<dim3((VV + 127) / 128, (BB * LQ) / 128), 256>>>(p_x1, fc2_W, fc2_b, out,
        BB * LQ, VV, H2, 0);
}